// round 4
// baseline (speedup 1.0000x reference)
#include <cuda_runtime.h>
#include <cstdint>
#include <math.h>

#define RET_ELEMS (256LL * 2048LL * 128LL)
#define DIFF_ELEMS (255LL * 2048LL * 128LL)

// ---------------------------------------------------------------------------
// helpers
// ---------------------------------------------------------------------------
__device__ __forceinline__ float gelu_exact(float x) {
    return 0.5f * x * (1.0f + erff(x * 0.7071067811865476f));
}
__device__ __forceinline__ unsigned f2tf32(float x) {
    unsigned r; asm("cvt.rna.tf32.f32 %0, %1;" : "=r"(r) : "f"(x)); return r;
}
__device__ __forceinline__ float tf32f(float x) { return __uint_as_float(f2tf32(x)); }

__device__ __forceinline__ void mma8(float* d, const unsigned* a, const unsigned* b) {
    asm volatile(
        "mma.sync.aligned.m16n8k8.row.col.f32.tf32.tf32.f32 "
        "{%0,%1,%2,%3}, {%4,%5,%6,%7}, {%8,%9}, {%0,%1,%2,%3};"
        : "+f"(d[0]), "+f"(d[1]), "+f"(d[2]), "+f"(d[3])
        : "r"(a[0]), "r"(a[1]), "r"(a[2]), "r"(a[3]), "r"(b[0]), "r"(b[1]));
}

// Pair-permuted layout (KS = K extent of the tile):
//   granule g of row holds k-pair (k, k+4); g = ((k>>3)<<2 | (k&3)) ^ ((row&3)<<2)
//   float index = row*KS + 2*g + ((k>>2)&1)
//   fragment load (float2): f2idx = row*(KS/2) + ((ks ^ (row&3))<<2) + tq,  ks = k0/8
// Scalar store index (used by fused epilogue-1):
__device__ __forceinline__ int ppidx(int row, int k, int KS) {
    int g = (((k >> 3) << 2) | (k & 3)) ^ ((row & 3) << 2);
    return row * KS + (g << 1) + ((k >> 2) & 1);
}

// ---------------------------------------------------------------------------
// Kernel A: ret = LayerNorm(gelu(gelu(X@W1+b1)@W2+b2) + X)
// 256 threads = 8 warps (4M x 2N). CTA tile 128 tokens.
// H computed in 8 chunks of 32 cols; Hs shares the W1-chunk buffer.
//   GEMM1: warp 32x16 (K=128); GEMM2: warp 32x64 (K=32/chunk, acc held).
// smem: Xf[128][128]pp 64KB | W1c/Hs 16KB | W2c 16KB | aux
// ---------------------------------------------------------------------------
#define FA_X   0
#define FA_W1  65536
#define FA_W2  81920
#define FA_B1  98304          // 256 f
#define FA_B2  (FA_B1+1024)   // 128 f
#define FA_G   (FA_B2+512)
#define FA_BE  (FA_G+512)
#define FA_PS  (FA_BE+512)    // float2[128][2] = 2048 B
#define FA_SZ  (FA_PS+2048)

__global__ __launch_bounds__(256, 2)
void fused_main_kernel(const float* __restrict__ src,
                       const float* __restrict__ W1, const float* __restrict__ b1,
                       const float* __restrict__ W2, const float* __restrict__ b2,
                       const float* __restrict__ gamma, const float* __restrict__ beta,
                       float* __restrict__ out_ret)
{
    extern __shared__ char smem[];
    float* Hsf = (float*)(smem + FA_W1);
    float* b1s = (float*)(smem + FA_B1);
    float* b2s = (float*)(smem + FA_B2);
    float* gs  = (float*)(smem + FA_G);
    float* bs  = (float*)(smem + FA_BE);
    float2* Ps = (float2*)(smem + FA_PS);

    const int tid = threadIdx.x, lane = tid & 31, wid = tid >> 5;
    const int group = lane >> 2, tq = lane & 3, g3 = group & 3;
    const int wm = wid & 3, wn = wid >> 2;
    const int r0 = wm * 32 + group;

    const int s  = blockIdx.y;
    const int b0 = blockIdx.x * 128;
    const float* Xg = src + ((size_t)s * 2048 + b0) * 128;

    // ---- stage X (tf32, pair-permuted, KS=128) ----
    {
        float4* Xf4 = (float4*)(smem + FA_X);
        for (int t = tid; t < 2048; t += 256) {
            int row = t >> 4, kp = t & 15;
            const float4* p = (const float4*)(Xg + row * 128 + kp * 8);
            float4 lo = p[0], hi = p[1];
            int base = row * 32 + ((kp ^ (row & 3)) << 1);
            Xf4[base]     = make_float4(tf32f(lo.x), tf32f(hi.x), tf32f(lo.y), tf32f(hi.y));
            Xf4[base + 1] = make_float4(tf32f(lo.z), tf32f(hi.z), tf32f(lo.w), tf32f(hi.w));
        }
    }
    b1s[tid] = b1[tid];
    if (tid < 128) { b2s[tid] = b2[tid]; gs[tid] = gamma[tid]; bs[tid] = beta[tid]; }

    float acc2[16][4];
#pragma unroll
    for (int i = 0; i < 16; i++) { acc2[i][0] = acc2[i][1] = acc2[i][2] = acc2[i][3] = 0.f; }

    const float2* Xf2  = (const float2*)(smem + FA_X);
    const float2* W1f2 = (const float2*)(smem + FA_W1);
    const float2* W2f2 = (const float2*)(smem + FA_W2);
    float2* W1st = (float2*)(smem + FA_W1);
    float2* W2st = (float2*)(smem + FA_W2);

    for (int c = 0; c < 8; ++c) {
        // ---- stage W1 chunk [n=32][k=128]pp and W2 chunk [n=128][k=32]pp ----
        for (int t = tid; t < 512; t += 256) {
            int kp = t >> 5, j = (t >> 3) & 3, n4 = t & 7;
            int k = kp * 8 + j;
            float4 lo = *(const float4*)(W1 + k * 256 + c * 32 + n4 * 4);
            float4 hi = *(const float4*)(W1 + (k + 4) * 256 + c * 32 + n4 * 4);
            const float* lof = &lo.x; const float* hif = &hi.x;
#pragma unroll
            for (int nn = 0; nn < 4; nn++) {
                int n = n4 * 4 + nn;
                W1st[n * 64 + ((kp ^ (n & 3)) << 2) + j] =
                    make_float2(tf32f(lof[nn]), tf32f(hif[nn]));
            }
        }
        for (int t = tid; t < 512; t += 256) {
            int kp = t >> 7, j = (t >> 5) & 3, n4 = t & 31;
            int k = kp * 8 + j;
            float4 lo = *(const float4*)(W2 + (c * 32 + k) * 128 + n4 * 4);
            float4 hi = *(const float4*)(W2 + (c * 32 + k + 4) * 128 + n4 * 4);
            const float* lof = &lo.x; const float* hif = &hi.x;
#pragma unroll
            for (int nn = 0; nn < 4; nn++) {
                int n = n4 * 4 + nn;
                W2st[n * 16 + ((kp ^ (n & 3)) << 2) + j] =
                    make_float2(tf32f(lof[nn]), tf32f(hif[nn]));
            }
        }
        __syncthreads();

        // ---- GEMM1: Hc = X @ W1c  (warp 32x16, K=128) ----
        float acc1[4][4];
#pragma unroll
        for (int i = 0; i < 4; i++) { acc1[i][0] = acc1[i][1] = acc1[i][2] = acc1[i][3] = 0.f; }
#pragma unroll
        for (int ks = 0; ks < 16; ks++) {
            int t = ((ks ^ g3) << 2) + tq;
            float2 a0 = Xf2[r0 * 64 + t];
            float2 a1 = Xf2[(r0 + 8) * 64 + t];
            float2 a2 = Xf2[(r0 + 16) * 64 + t];
            float2 a3 = Xf2[(r0 + 24) * 64 + t];
            unsigned am0[4] = {__float_as_uint(a0.x), __float_as_uint(a1.x),
                               __float_as_uint(a0.y), __float_as_uint(a1.y)};
            unsigned am1[4] = {__float_as_uint(a2.x), __float_as_uint(a3.x),
                               __float_as_uint(a2.y), __float_as_uint(a3.y)};
#pragma unroll
            for (int nt = 0; nt < 2; nt++) {
                int n0 = wn * 16 + nt * 8 + group;
                float2 b = W1f2[n0 * 64 + t];
                unsigned bf[2] = {__float_as_uint(b.x), __float_as_uint(b.y)};
                mma8(acc1[nt],     am0, bf);
                mma8(acc1[2 + nt], am1, bf);
            }
        }
        __syncthreads();   // GEMM1 reads of W1c done

        // ---- epilogue-1: Hs = tf32(gelu(acc1 + b1)), overwrites W1c buffer ----
#pragma unroll
        for (int mt = 0; mt < 2; mt++) {
#pragma unroll
            for (int nt = 0; nt < 2; nt++) {
                int col = wn * 16 + nt * 8 + 2 * tq;
                int rA = r0 + mt * 16, rB = rA + 8;
                float bi0 = b1s[c * 32 + col], bi1 = b1s[c * 32 + col + 1];
                float* v = acc1[mt * 2 + nt];
                Hsf[ppidx(rA, col,     32)] = tf32f(gelu_exact(v[0] + bi0));
                Hsf[ppidx(rA, col + 1, 32)] = tf32f(gelu_exact(v[1] + bi1));
                Hsf[ppidx(rB, col,     32)] = tf32f(gelu_exact(v[2] + bi0));
                Hsf[ppidx(rB, col + 1, 32)] = tf32f(gelu_exact(v[3] + bi1));
            }
        }
        __syncthreads();

        // ---- GEMM2: acc2 += Hc @ W2c  (warp 32x64, K=32) ----
#pragma unroll
        for (int ks = 0; ks < 4; ks++) {
            int t = ((ks ^ g3) << 2) + tq;
            float2 a0 = W1f2[r0 * 16 + t];          // Hs lives in W1 buffer
            float2 a1 = W1f2[(r0 + 8) * 16 + t];
            float2 a2 = W1f2[(r0 + 16) * 16 + t];
            float2 a3 = W1f2[(r0 + 24) * 16 + t];
            unsigned am0[4] = {__float_as_uint(a0.x), __float_as_uint(a1.x),
                               __float_as_uint(a0.y), __float_as_uint(a1.y)};
            unsigned am1[4] = {__float_as_uint(a2.x), __float_as_uint(a3.x),
                               __float_as_uint(a2.y), __float_as_uint(a3.y)};
#pragma unroll
            for (int nt = 0; nt < 8; nt++) {
                int n0 = wn * 64 + nt * 8 + group;
                float2 b = W2f2[n0 * 16 + t];
                unsigned bf[2] = {__float_as_uint(b.x), __float_as_uint(b.y)};
                mma8(acc2[nt],     am0, bf);
                mma8(acc2[8 + nt], am1, bf);
            }
        }
        __syncthreads();   // before next chunk restages W1c/W2c
    }

    // ---- epilogue-2: r = gelu(acc2 + b2) + X ; LayerNorm ; store ----
    float sums[4] = {0, 0, 0, 0}, sqs[4] = {0, 0, 0, 0};
    const float2* Xg2 = (const float2*)Xg;
#pragma unroll
    for (int mt = 0; mt < 2; mt++) {
#pragma unroll
        for (int nt = 0; nt < 8; nt++) {
            int col = wn * 64 + nt * 8 + 2 * tq;
            int rA = r0 + mt * 16, rB = rA + 8;
            float2 xa = Xg2[rA * 64 + (col >> 1)];
            float2 xb = Xg2[rB * 64 + (col >> 1)];
            float* v = acc2[mt * 8 + nt];
            v[0] = gelu_exact(v[0] + b2s[col])     + xa.x;
            v[1] = gelu_exact(v[1] + b2s[col + 1]) + xa.y;
            v[2] = gelu_exact(v[2] + b2s[col])     + xb.x;
            v[3] = gelu_exact(v[3] + b2s[col + 1]) + xb.y;
            sums[mt * 2]     += v[0] + v[1]; sqs[mt * 2]     += v[0] * v[0] + v[1] * v[1];
            sums[mt * 2 + 1] += v[2] + v[3]; sqs[mt * 2 + 1] += v[2] * v[2] + v[3] * v[3];
        }
    }
#pragma unroll
    for (int j = 0; j < 4; j++) {
#pragma unroll
        for (int o = 1; o < 4; o <<= 1) {
            sums[j] += __shfl_xor_sync(0xffffffffu, sums[j], o);
            sqs[j]  += __shfl_xor_sync(0xffffffffu, sqs[j],  o);
        }
    }
    if (tq == 0) {
#pragma unroll
        for (int j = 0; j < 4; j++) Ps[(r0 + j * 8) * 2 + wn] = make_float2(sums[j], sqs[j]);
    }
    __syncthreads();
    float mus[4], rss[4];
#pragma unroll
    for (int j = 0; j < 4; j++) {
        int row = r0 + j * 8;
        float2 p0 = Ps[row * 2], p1 = Ps[row * 2 + 1];
        float mu  = (p0.x + p1.x) * (1.f / 128.f);
        float var = (p0.y + p1.y) * (1.f / 128.f) - mu * mu;
        mus[j] = mu; rss[j] = rsqrtf(var + 1e-5f);
    }
    float2* og2 = (float2*)(out_ret + ((size_t)s * 2048 + b0) * 128);
#pragma unroll
    for (int mt = 0; mt < 2; mt++) {
#pragma unroll
        for (int nt = 0; nt < 8; nt++) {
            int col = wn * 64 + nt * 8 + 2 * tq;
            int rA = r0 + mt * 16, rB = rA + 8;
            float* v = acc2[mt * 8 + nt];
            float muA = mus[mt * 2],     rsA = rss[mt * 2];
            float muB = mus[mt * 2 + 1], rsB = rss[mt * 2 + 1];
            og2[rA * 64 + (col >> 1)] =
                make_float2((v[0] - muA) * rsA * gs[col]     + bs[col],
                            (v[1] - muA) * rsA * gs[col + 1] + bs[col + 1]);
            og2[rB * 64 + (col >> 1)] =
                make_float2((v[2] - muB) * rsB * gs[col]     + bs[col],
                            (v[3] - muB) * rsB * gs[col + 1] + bs[col + 1]);
        }
    }
}

// ---------------------------------------------------------------------------
// Kernel B: diffs[s-1] = gelu([X_{s-1} | X_s] @ Wb + bb)
// 256 threads = 8 warps (4M x 2N), warp 32x64, CTA tile 128 tokens.
// K=256 processed in 4 quarters of 64; As/Wq staged per quarter.
// smem: As[128][64]pp 32KB | Wq[128][64]pp 32KB | bbs
// ---------------------------------------------------------------------------
#define BB_A   0
#define BB_W   32768
#define BB_BB  65536
#define BB_SZ  (BB_BB + 512)

__global__ __launch_bounds__(256, 2)
void bracket_kernel(const float* __restrict__ src,
                    const float* __restrict__ Wb, const float* __restrict__ bb,
                    float* __restrict__ out_diffs, float* __restrict__ cond)
{
    extern __shared__ char smem[];
    float* bbs = (float*)(smem + BB_BB);

    const int tid = threadIdx.x, lane = tid & 31, wid = tid >> 5;
    const int group = lane >> 2, tq = lane & 3, g3 = group & 3;
    const int wm = wid & 3, wn = wid >> 2;
    const int r0 = wm * 32 + group;

    const int s  = blockIdx.y + 1;
    const int b0 = blockIdx.x * 128;
    if (blockIdx.x == 0 && blockIdx.y == 0 && tid < 3) cond[tid] = 0.f;

    const float* Xgp = src + ((size_t)(s - 1) * 2048 + b0) * 128;
    const float* Xgc = src + ((size_t)s * 2048 + b0) * 128;
    if (tid < 128) bbs[tid] = bb[tid];

    float acc[16][4];
#pragma unroll
    for (int i = 0; i < 16; i++) { acc[i][0] = acc[i][1] = acc[i][2] = acc[i][3] = 0.f; }

    float4* As4 = (float4*)(smem + BB_A);
    float2* Wst = (float2*)(smem + BB_W);
    const float2* As2 = (const float2*)(smem + BB_A);
    const float2* Wq2 = (const float2*)(smem + BB_W);

    for (int q = 0; q < 4; ++q) {
        const float* Xq = (q < 2 ? Xgp : Xgc) + (q & 1) * 64;

        // stage As [128 rows][64 k]pp
        for (int t = tid; t < 1024; t += 256) {
            int row = t >> 3, kp = t & 7;
            const float4* p = (const float4*)(Xq + row * 128 + kp * 8);
            float4 lo = p[0], hi = p[1];
            int base = row * 16 + ((kp ^ (row & 3)) << 1);
            As4[base]     = make_float4(tf32f(lo.x), tf32f(hi.x), tf32f(lo.y), tf32f(hi.y));
            As4[base + 1] = make_float4(tf32f(lo.z), tf32f(hi.z), tf32f(lo.w), tf32f(hi.w));
        }
        // stage Wq [128 n][64 k]pp from Wb rows q*64..q*64+64
        for (int t = tid; t < 1024; t += 256) {
            int kp = t >> 7, j = (t >> 5) & 3, n4 = t & 31;
            int k = q * 64 + kp * 8 + j;
            float4 lo = *(const float4*)(Wb + k * 128 + n4 * 4);
            float4 hi = *(const float4*)(Wb + (k + 4) * 128 + n4 * 4);
            const float* lof = &lo.x; const float* hif = &hi.x;
#pragma unroll
            for (int nn = 0; nn < 4; nn++) {
                int n = n4 * 4 + nn;
                Wst[n * 32 + ((kp ^ (n & 3)) << 2) + j] =
                    make_float2(tf32f(lof[nn]), tf32f(hif[nn]));
            }
        }
        __syncthreads();

        // GEMM quarter: warp 32x64, K=64 (8 ksteps)
#pragma unroll
        for (int ks = 0; ks < 8; ks++) {
            int t = ((ks ^ g3) << 2) + tq;
            float2 a0 = As2[r0 * 32 + t];
            float2 a1 = As2[(r0 + 8) * 32 + t];
            float2 a2 = As2[(r0 + 16) * 32 + t];
            float2 a3 = As2[(r0 + 24) * 32 + t];
            unsigned am0[4] = {__float_as_uint(a0.x), __float_as_uint(a1.x),
                               __float_as_uint(a0.y), __float_as_uint(a1.y)};
            unsigned am1[4] = {__float_as_uint(a2.x), __float_as_uint(a3.x),
                               __float_as_uint(a2.y), __float_as_uint(a3.y)};
#pragma unroll
            for (int nt = 0; nt < 8; nt++) {
                int n0 = wn * 64 + nt * 8 + group;
                float2 b = Wq2[n0 * 32 + t];
                unsigned bf[2] = {__float_as_uint(b.x), __float_as_uint(b.y)};
                mma8(acc[nt],     am0, bf);
                mma8(acc[8 + nt], am1, bf);
            }
        }
        __syncthreads();   // before restaging
    }

    // epilogue: gelu(acc + bb) -> diffs
    float2* og2 = (float2*)(out_diffs + ((size_t)(s - 1) * 2048 + b0) * 128);
#pragma unroll
    for (int mt = 0; mt < 2; mt++) {
#pragma unroll
        for (int nt = 0; nt < 8; nt++) {
            int col = wn * 64 + nt * 8 + 2 * tq;
            int rA = r0 + mt * 16, rB = rA + 8;
            float bi0 = bbs[col], bi1 = bbs[col + 1];
            float* v = acc[mt * 8 + nt];
            og2[rA * 64 + (col >> 1)] = make_float2(gelu_exact(v[0] + bi0),
                                                    gelu_exact(v[1] + bi1));
            og2[rB * 64 + (col >> 1)] = make_float2(gelu_exact(v[2] + bi0),
                                                    gelu_exact(v[3] + bi1));
        }
    }
}

// ---------------------------------------------------------------------------
// launcher
// ---------------------------------------------------------------------------
extern "C" void kernel_launch(void* const* d_in, const int* in_sizes, int n_in,
                              void* d_out, int out_size)
{
    const float* src   = (const float*)d_in[0];
    const float* Wb    = (const float*)d_in[1];
    const float* bb    = (const float*)d_in[2];
    const float* W1    = (const float*)d_in[3];
    const float* b1    = (const float*)d_in[4];
    const float* W2    = (const float*)d_in[5];
    const float* b2    = (const float*)d_in[6];
    const float* gamma = (const float*)d_in[7];
    const float* beta  = (const float*)d_in[8];
    float* out = (float*)d_out;

    cudaFuncSetAttribute(fused_main_kernel, cudaFuncAttributeMaxDynamicSharedMemorySize, FA_SZ);
    cudaFuncSetAttribute(bracket_kernel,    cudaFuncAttributeMaxDynamicSharedMemorySize, BB_SZ);

    dim3 gA(16, 256);
    dim3 gB(16, 255);
    fused_main_kernel<<<gA, 256, FA_SZ>>>(src, W1, b1, W2, b2, gamma, beta, out);
    bracket_kernel<<<gB, 256, BB_SZ>>>(src, Wb, bb,
                                       out + RET_ELEMS,
                                       out + RET_ELEMS + DIFF_ELEMS);
}

// round 7
// speedup vs baseline: 1.2245x; 1.2245x over previous
#include <cuda_runtime.h>
#include <cstdint>
#include <math.h>

#define RET_ELEMS (256LL * 2048LL * 128LL)
#define DIFF_ELEMS (255LL * 2048LL * 128LL)

// Pre-transposed, tf32-pre-rounded weights: [n][k] row-major.
__device__ float g_Wb[128 * 256];
__device__ float g_W1[256 * 128];
__device__ float g_W2[128 * 256];

// ---------------------------------------------------------------------------
// helpers
// ---------------------------------------------------------------------------
__device__ __forceinline__ float gelu_exact(float x) {
    return 0.5f * x * (1.0f + erff(x * 0.7071067811865476f));
}
__device__ __forceinline__ unsigned f2tf32(float x) {
    unsigned r; asm("cvt.rna.tf32.f32 %0, %1;" : "=r"(r) : "f"(x)); return r;
}
__device__ __forceinline__ float tf32f(float x) { return __uint_as_float(f2tf32(x)); }

__device__ __forceinline__ uint32_t smem_u32(const void* p) {
    uint32_t a;
    asm("{ .reg .u64 t; cvta.to.shared.u64 t, %1; cvt.u32.u64 %0, t; }" : "=r"(a) : "l"(p));
    return a;
}

__device__ __forceinline__ void mma8(float* d, const unsigned* a, const unsigned* b) {
    asm volatile(
        "mma.sync.aligned.m16n8k8.row.col.f32.tf32.tf32.f32 "
        "{%0,%1,%2,%3}, {%4,%5,%6,%7}, {%8,%9}, {%0,%1,%2,%3};"
        : "+f"(d[0]), "+f"(d[1]), "+f"(d[2]), "+f"(d[3])
        : "r"(a[0]), "r"(a[1]), "r"(a[2]), "r"(a[3]), "r"(b[0]), "r"(b[1]));
}

#define LDSM4(R, addr) \
    asm volatile("ldmatrix.sync.aligned.m8n8.x4.shared.b16 {%0,%1,%2,%3}, [%4];" \
                 : "=r"((R)[0]), "=r"((R)[1]), "=r"((R)[2]), "=r"((R)[3]) : "r"(addr))

// ---------------------------------------------------------------------------
// prep: transpose + tf32-round weights into __device__ scratch
// ---------------------------------------------------------------------------
__global__ void prep_weights(const float* __restrict__ Wb,
                             const float* __restrict__ W1,
                             const float* __restrict__ W2)
{
    int i = blockIdx.x * 256 + threadIdx.x;       // 0 .. 24575 float4 slots
    const float* src; float* dst; int N, K, idx;
    if (i < 8192)       { src = Wb; dst = g_Wb; N = 128; K = 256; idx = i; }
    else if (i < 16384) { src = W1; dst = g_W1; N = 256; K = 128; idx = i - 8192; }
    else                { src = W2; dst = g_W2; N = 128; K = 256; idx = i - 16384; }
    int kq = K >> 2;
    int n = idx / kq, k4 = idx % kq;
    float4 o;
    o.x = tf32f(src[(k4 * 4 + 0) * N + n]);
    o.y = tf32f(src[(k4 * 4 + 1) * N + n]);
    o.z = tf32f(src[(k4 * 4 + 2) * N + n]);
    o.w = tf32f(src[(k4 * 4 + 3) * N + n]);
    *reinterpret_cast<float4*>(&dst[n * K + k4 * 4]) = o;
}

// ---------------------------------------------------------------------------
// Kernel A: ret = LayerNorm(gelu(gelu(X@W1+b1)@W2+b2) + X)
// 512 thr = 16 warps (4M x 4N), CTA tile 128 tokens, H in 4 chunks of 64.
// smem strides (floats): X/W1C 132, H/W2C 68
// ---------------------------------------------------------------------------
#define FA_X    0                      // 128*132*4 = 67584
#define FA_W1C  67584                  // 64*132*4  = 33792
#define FA_W2C  101376                 // 128*68*4  = 34816
#define FA_H    136192                 // 128*68*4  = 34816
#define FA_B1   171008                 // 1024
#define FA_B2   172032                 // 512
#define FA_G    172544                 // 512
#define FA_BE   173056                 // 512
#define FA_PS   173568                 // float2[128][4] = 4096
#define FA_SZ   177664

__global__ __launch_bounds__(512, 1)
void fused_main_kernel(const float* __restrict__ src,
                       const float* __restrict__ b1, const float* __restrict__ b2,
                       const float* __restrict__ gamma, const float* __restrict__ beta,
                       float* __restrict__ out_ret)
{
    extern __shared__ char smem[];
    const uint32_t sb = smem_u32(smem);
    float* Xs  = (float*)(smem + FA_X);
    float* W1C = (float*)(smem + FA_W1C);
    float* W2C = (float*)(smem + FA_W2C);
    float* Hs  = (float*)(smem + FA_H);
    float* b1s = (float*)(smem + FA_B1);
    float* b2s = (float*)(smem + FA_B2);
    float* gs  = (float*)(smem + FA_G);
    float* bs  = (float*)(smem + FA_BE);
    float2* Ps = (float2*)(smem + FA_PS);

    const int tid = threadIdx.x, lane = tid & 31, wid = tid >> 5;
    const int group = lane >> 2, tq = lane & 3;
    const int wm = wid & 3, wn = wid >> 2;       // 4M x 4N
    const int r0 = wm * 32 + group;

    const int s  = blockIdx.y;
    const int b0 = blockIdx.x * 128;
    const float* Xg = src + ((size_t)s * 2048 + b0) * 128;

    // ---- stage X (tf32), vectorized, stride 132 ----
    for (int u = tid; u < 4096; u += 512) {
        int row = u >> 5, c4 = u & 31;
        float4 v = reinterpret_cast<const float4*>(Xg + row * 128)[c4];
        float4 t = make_float4(tf32f(v.x), tf32f(v.y), tf32f(v.z), tf32f(v.w));
        *reinterpret_cast<float4*>(&Xs[row * 132 + c4 * 4]) = t;
    }
    if (tid < 256) b1s[tid] = b1[tid];
    if (tid < 128) { b2s[tid] = b2[tid]; gs[tid] = gamma[tid]; bs[tid] = beta[tid]; }

    // per-lane LDSM addresses
    const int lm = lane & 15, lh = lane >> 4;            // A: row-in-16, k-half
    const int bn = (lane & 7) + ((lane >> 4) << 3);      // B: n-in-16
    const int bk = ((lane >> 3) & 1) * 16;               // B: k-half bytes
    const uint32_t a1base0 = sb + FA_X + (uint32_t)(wm * 32 + lm) * 528 + lh * 16;
    const uint32_t a1base1 = a1base0 + 16 * 528;
    const uint32_t b1base  = sb + FA_W1C + (uint32_t)(wn * 16 + bn) * 528 + bk;
    const uint32_t a2base0 = sb + FA_H + (uint32_t)(wm * 32 + lm) * 272 + lh * 16;
    const uint32_t a2base1 = a2base0 + 16 * 272;
    const uint32_t b2base0 = sb + FA_W2C + (uint32_t)(wn * 32 + bn) * 272 + bk;
    const uint32_t b2base1 = b2base0 + 16 * 272;

    float acc2[8][4];
#pragma unroll
    for (int i = 0; i < 8; i++) { acc2[i][0] = acc2[i][1] = acc2[i][2] = acc2[i][3] = 0.f; }

    for (int c = 0; c < 4; ++c) {
        // ---- stage W1 chunk (rows c*64..+64) and W2 chunk (k-slice c*64) ----
        for (int u = tid; u < 2048; u += 512) {
            int row = u >> 5, k4 = u & 31;
            *reinterpret_cast<float4*>(&W1C[row * 132 + k4 * 4]) =
                *reinterpret_cast<const float4*>(&g_W1[(c * 64 + row) * 128 + k4 * 4]);
        }
        for (int u = tid; u < 2048; u += 512) {
            int n = u >> 4, k4 = u & 15;
            *reinterpret_cast<float4*>(&W2C[n * 68 + k4 * 4]) =
                *reinterpret_cast<const float4*>(&g_W2[n * 256 + c * 64 + k4 * 4]);
        }
        __syncthreads();

        // ---- GEMM1: Hc = X @ W1c  (warp 32x16, K=128, 16 ksteps) ----
        float acc1[4][4];
#pragma unroll
        for (int i = 0; i < 4; i++) { acc1[i][0] = acc1[i][1] = acc1[i][2] = acc1[i][3] = 0.f; }
#pragma unroll
        for (int ks = 0; ks < 16; ks++) {
            unsigned A0[4], A1[4], B0[4];
            LDSM4(A0, a1base0 + ks * 32);
            LDSM4(A1, a1base1 + ks * 32);
            LDSM4(B0, b1base + ks * 32);
            mma8(acc1[0], A0, B0);     mma8(acc1[1], A0, B0 + 2);
            mma8(acc1[2], A1, B0);     mma8(acc1[3], A1, B0 + 2);
        }

        // ---- epilogue-1: H = tf32(gelu(acc1 + b1)) ----
#pragma unroll
        for (int mt = 0; mt < 2; mt++) {
#pragma unroll
            for (int nt = 0; nt < 2; nt++) {
                int col = wn * 16 + nt * 8 + 2 * tq;
                int rA = r0 + mt * 16, rB = rA + 8;
                float bi0 = b1s[c * 64 + col], bi1 = b1s[c * 64 + col + 1];
                float* v = acc1[mt * 2 + nt];
                *reinterpret_cast<float2*>(&Hs[rA * 68 + col]) =
                    make_float2(tf32f(gelu_exact(v[0] + bi0)), tf32f(gelu_exact(v[1] + bi1)));
                *reinterpret_cast<float2*>(&Hs[rB * 68 + col]) =
                    make_float2(tf32f(gelu_exact(v[2] + bi0)), tf32f(gelu_exact(v[3] + bi1)));
            }
        }
        __syncthreads();

        // ---- GEMM2: acc2 += Hc @ W2c (warp 32x32, K=64, 8 ksteps) ----
#pragma unroll
        for (int ks = 0; ks < 8; ks++) {
            unsigned A0[4], A1[4], B0[4], B1[4];
            LDSM4(A0, a2base0 + ks * 32);
            LDSM4(A1, a2base1 + ks * 32);
            LDSM4(B0, b2base0 + ks * 32);
            LDSM4(B1, b2base1 + ks * 32);
            mma8(acc2[0], A0, B0);     mma8(acc2[1], A0, B0 + 2);
            mma8(acc2[2], A0, B1);     mma8(acc2[3], A0, B1 + 2);
            mma8(acc2[4], A1, B0);     mma8(acc2[5], A1, B0 + 2);
            mma8(acc2[6], A1, B1);     mma8(acc2[7], A1, B1 + 2);
        }
        __syncthreads();   // before restaging W1C/W2C/Hs
    }

    // ---- epilogue-2: r = gelu(acc2+b2)+X ; LayerNorm ; store ----
    float sums[4] = {0, 0, 0, 0}, sqs[4] = {0, 0, 0, 0};
    const float2* Xg2 = (const float2*)Xg;
#pragma unroll
    for (int mt = 0; mt < 2; mt++) {
#pragma unroll
        for (int nt = 0; nt < 4; nt++) {
            int col = wn * 32 + nt * 8 + 2 * tq;
            int rA = r0 + mt * 16, rB = rA + 8;
            float2 xa = Xg2[rA * 64 + (col >> 1)];
            float2 xb = Xg2[rB * 64 + (col >> 1)];
            float* v = acc2[mt * 4 + nt];
            v[0] = gelu_exact(v[0] + b2s[col])     + xa.x;
            v[1] = gelu_exact(v[1] + b2s[col + 1]) + xa.y;
            v[2] = gelu_exact(v[2] + b2s[col])     + xb.x;
            v[3] = gelu_exact(v[3] + b2s[col + 1]) + xb.y;
            sums[mt * 2]     += v[0] + v[1]; sqs[mt * 2]     += v[0] * v[0] + v[1] * v[1];
            sums[mt * 2 + 1] += v[2] + v[3]; sqs[mt * 2 + 1] += v[2] * v[2] + v[3] * v[3];
        }
    }
#pragma unroll
    for (int j = 0; j < 4; j++) {
#pragma unroll
        for (int o = 1; o < 4; o <<= 1) {
            sums[j] += __shfl_xor_sync(0xffffffffu, sums[j], o);
            sqs[j]  += __shfl_xor_sync(0xffffffffu, sqs[j],  o);
        }
    }
    if (tq == 0) {
#pragma unroll
        for (int j = 0; j < 4; j++) Ps[(r0 + j * 8) * 4 + wn] = make_float2(sums[j], sqs[j]);
    }
    __syncthreads();
    float mus[4], rss[4];
#pragma unroll
    for (int j = 0; j < 4; j++) {
        int row = r0 + j * 8;
        float ssum = 0.f, ssq = 0.f;
#pragma unroll
        for (int w = 0; w < 4; w++) { float2 p = Ps[row * 4 + w]; ssum += p.x; ssq += p.y; }
        float mu  = ssum * (1.f / 128.f);
        float var = ssq * (1.f / 128.f) - mu * mu;
        mus[j] = mu; rss[j] = rsqrtf(var + 1e-5f);
    }
    float2* og2 = (float2*)(out_ret + ((size_t)s * 2048 + b0) * 128);
#pragma unroll
    for (int mt = 0; mt < 2; mt++) {
#pragma unroll
        for (int nt = 0; nt < 4; nt++) {
            int col = wn * 32 + nt * 8 + 2 * tq;
            int rA = r0 + mt * 16, rB = rA + 8;
            float* v = acc2[mt * 4 + nt];
            float muA = mus[mt * 2],     rsA = rss[mt * 2];
            float muB = mus[mt * 2 + 1], rsB = rss[mt * 2 + 1];
            og2[rA * 64 + (col >> 1)] =
                make_float2((v[0] - muA) * rsA * gs[col]     + bs[col],
                            (v[1] - muA) * rsA * gs[col + 1] + bs[col + 1]);
            og2[rB * 64 + (col >> 1)] =
                make_float2((v[2] - muB) * rsB * gs[col]     + bs[col],
                            (v[3] - muB) * rsB * gs[col + 1] + bs[col + 1]);
        }
    }
}

// ---------------------------------------------------------------------------
// Kernel B: diffs[s-1] = gelu([X_{s-1} | X_s] @ Wb + bb)
// 512 thr = 16 warps (4M x 4N), warp 32x32, K=256 as two 128-halves.
// ---------------------------------------------------------------------------
#define BB_XP   0                      // 67584
#define BB_XC   67584                  // 67584
#define BB_WH   135168                 // 67584
#define BB_BB   202752                 // 512
#define BB_SZ   203264

__global__ __launch_bounds__(512, 1)
void bracket_kernel(const float* __restrict__ src,
                    const float* __restrict__ bb,
                    float* __restrict__ out_diffs, float* __restrict__ cond)
{
    extern __shared__ char smem[];
    const uint32_t sb = smem_u32(smem);
    float* Xp  = (float*)(smem + BB_XP);
    float* Xc  = (float*)(smem + BB_XC);
    float* Wh  = (float*)(smem + BB_WH);
    float* bbs = (float*)(smem + BB_BB);

    const int tid = threadIdx.x, lane = tid & 31, wid = tid >> 5;
    const int group = lane >> 2, tq = lane & 3;
    const int wm = wid & 3, wn = wid >> 2;
    const int r0 = wm * 32 + group;

    const int s  = blockIdx.y + 1;
    const int b0 = blockIdx.x * 128;
    if (blockIdx.x == 0 && blockIdx.y == 0 && tid < 3) cond[tid] = 0.f;

    const float* Xgp = src + ((size_t)(s - 1) * 2048 + b0) * 128;
    const float* Xgc = src + ((size_t)s * 2048 + b0) * 128;

    // stage both X tiles (tf32), stride 132
    for (int u = tid; u < 4096; u += 512) {
        int row = u >> 5, c4 = u & 31;
        float4 vp = reinterpret_cast<const float4*>(Xgp + row * 128)[c4];
        float4 vc = reinterpret_cast<const float4*>(Xgc + row * 128)[c4];
        *reinterpret_cast<float4*>(&Xp[row * 132 + c4 * 4]) =
            make_float4(tf32f(vp.x), tf32f(vp.y), tf32f(vp.z), tf32f(vp.w));
        *reinterpret_cast<float4*>(&Xc[row * 132 + c4 * 4]) =
            make_float4(tf32f(vc.x), tf32f(vc.y), tf32f(vc.z), tf32f(vc.w));
    }
    if (tid < 128) bbs[tid] = bb[tid];

    const int lm = lane & 15, lh = lane >> 4;
    const int bn = (lane & 7) + ((lane >> 4) << 3);
    const int bk = ((lane >> 3) & 1) * 16;
    const uint32_t aP0 = sb + BB_XP + (uint32_t)(wm * 32 + lm) * 528 + lh * 16;
    const uint32_t aP1 = aP0 + 16 * 528;
    const uint32_t aC0 = sb + BB_XC + (uint32_t)(wm * 32 + lm) * 528 + lh * 16;
    const uint32_t aC1 = aC0 + 16 * 528;
    const uint32_t bW0 = sb + BB_WH + (uint32_t)(wn * 32 + bn) * 528 + bk;
    const uint32_t bW1 = bW0 + 16 * 528;

    float acc[8][4];
#pragma unroll
    for (int i = 0; i < 8; i++) { acc[i][0] = acc[i][1] = acc[i][2] = acc[i][3] = 0.f; }

    for (int h = 0; h < 2; ++h) {
        // stage Wb half: g_Wb all 128 n-rows, k-slice h*128..+128
        // (128 floats/row = 32 float4/row -> 4096 float4 total)
        for (int u = tid; u < 4096; u += 512) {
            int n = u >> 5, k4 = u & 31;
            *reinterpret_cast<float4*>(&Wh[n * 132 + k4 * 4]) =
                *reinterpret_cast<const float4*>(&g_Wb[n * 256 + h * 128 + k4 * 4]);
        }
        __syncthreads();

        const uint32_t a0b = h ? aC0 : aP0;
        const uint32_t a1b = h ? aC1 : aP1;
#pragma unroll
        for (int ks = 0; ks < 16; ks++) {
            unsigned A0[4], A1[4], B0[4], B1[4];
            LDSM4(A0, a0b + ks * 32);
            LDSM4(A1, a1b + ks * 32);
            LDSM4(B0, bW0 + ks * 32);
            LDSM4(B1, bW1 + ks * 32);
            mma8(acc[0], A0, B0);     mma8(acc[1], A0, B0 + 2);
            mma8(acc[2], A0, B1);     mma8(acc[3], A0, B1 + 2);
            mma8(acc[4], A1, B0);     mma8(acc[5], A1, B0 + 2);
            mma8(acc[6], A1, B1);     mma8(acc[7], A1, B1 + 2);
        }
        __syncthreads();   // before restaging Wh
    }

    // epilogue: gelu(acc + bb) -> diffs
    float2* og2 = (float2*)(out_diffs + ((size_t)(s - 1) * 2048 + b0) * 128);
#pragma unroll
    for (int mt = 0; mt < 2; mt++) {
#pragma unroll
        for (int nt = 0; nt < 4; nt++) {
            int col = wn * 32 + nt * 8 + 2 * tq;
            int rA = r0 + mt * 16, rB = rA + 8;
            float bi0 = bbs[col], bi1 = bbs[col + 1];
            float* v = acc[mt * 4 + nt];
            og2[rA * 64 + (col >> 1)] = make_float2(gelu_exact(v[0] + bi0),
                                                    gelu_exact(v[1] + bi1));
            og2[rB * 64 + (col >> 1)] = make_float2(gelu_exact(v[2] + bi0),
                                                    gelu_exact(v[3] + bi1));
        }
    }
}

// ---------------------------------------------------------------------------
// launcher
// ---------------------------------------------------------------------------
extern "C" void kernel_launch(void* const* d_in, const int* in_sizes, int n_in,
                              void* d_out, int out_size)
{
    const float* src   = (const float*)d_in[0];
    const float* Wb    = (const float*)d_in[1];
    const float* bb    = (const float*)d_in[2];
    const float* W1    = (const float*)d_in[3];
    const float* b1    = (const float*)d_in[4];
    const float* W2    = (const float*)d_in[5];
    const float* b2    = (const float*)d_in[6];
    const float* gamma = (const float*)d_in[7];
    const float* beta  = (const float*)d_in[8];
    float* out = (float*)d_out;

    cudaFuncSetAttribute(fused_main_kernel, cudaFuncAttributeMaxDynamicSharedMemorySize, FA_SZ);
    cudaFuncSetAttribute(bracket_kernel,    cudaFuncAttributeMaxDynamicSharedMemorySize, BB_SZ);

    prep_weights<<<96, 256>>>(Wb, W1, W2);

    dim3 gA(16, 256);
    dim3 gB(16, 255);
    fused_main_kernel<<<gA, 512, FA_SZ>>>(src, b1, b2, gamma, beta, out);
    bracket_kernel<<<gB, 512, BB_SZ>>>(src, bb,
                                       out + RET_ELEMS,
                                       out + RET_ELEMS + DIFF_ELEMS);
}

// round 8
// speedup vs baseline: 1.3531x; 1.1051x over previous
#include <cuda_runtime.h>
#include <cstdint>
#include <math.h>

#define RET_ELEMS (256LL * 2048LL * 128LL)
#define DIFF_ELEMS (255LL * 2048LL * 128LL)

// Pre-transposed, tf32-pre-rounded weights: [n][k] row-major.
__device__ float g_Wb[128 * 256];
__device__ float g_W1[256 * 128];
__device__ float g_W2[128 * 256];

// ---------------------------------------------------------------------------
// helpers
// ---------------------------------------------------------------------------
__device__ __forceinline__ float gelu_exact(float x) {
    return 0.5f * x * (1.0f + erff(x * 0.7071067811865476f));
}
__device__ __forceinline__ unsigned f2tf32(float x) {
    unsigned r; asm("cvt.rna.tf32.f32 %0, %1;" : "=r"(r) : "f"(x)); return r;
}
__device__ __forceinline__ float tf32f(float x) { return __uint_as_float(f2tf32(x)); }

__device__ __forceinline__ uint32_t smem_u32(const void* p) {
    uint32_t a;
    asm("{ .reg .u64 t; cvta.to.shared.u64 t, %1; cvt.u32.u64 %0, t; }" : "=r"(a) : "l"(p));
    return a;
}

__device__ __forceinline__ void mma8(float* d, const unsigned* a, const unsigned* b) {
    asm volatile(
        "mma.sync.aligned.m16n8k8.row.col.f32.tf32.tf32.f32 "
        "{%0,%1,%2,%3}, {%4,%5,%6,%7}, {%8,%9}, {%0,%1,%2,%3};"
        : "+f"(d[0]), "+f"(d[1]), "+f"(d[2]), "+f"(d[3])
        : "r"(a[0]), "r"(a[1]), "r"(a[2]), "r"(a[3]), "r"(b[0]), "r"(b[1]));
}

#define LDSM4(R, addr) \
    asm volatile("ldmatrix.sync.aligned.m8n8.x4.shared.b16 {%0,%1,%2,%3}, [%4];" \
                 : "=r"((R)[0]), "=r"((R)[1]), "=r"((R)[2]), "=r"((R)[3]) : "r"(addr))

__device__ __forceinline__ void cp16(uint32_t dst, const void* src) {
    asm volatile("cp.async.cg.shared.global [%0], [%1], 16;" :: "r"(dst), "l"(src));
}
#define CP_COMMIT asm volatile("cp.async.commit_group;" ::: "memory")
#define CP_WAIT0  asm volatile("cp.async.wait_group 0;"  ::: "memory")

// ---------------------------------------------------------------------------
// prep: transpose + tf32-round weights into __device__ scratch
// ---------------------------------------------------------------------------
__global__ void prep_weights(const float* __restrict__ Wb,
                             const float* __restrict__ W1,
                             const float* __restrict__ W2)
{
    int i = blockIdx.x * 256 + threadIdx.x;       // 0 .. 24575 float4 slots
    const float* src; float* dst; int N, K, idx;
    if (i < 8192)       { src = Wb; dst = g_Wb; N = 128; K = 256; idx = i; }
    else if (i < 16384) { src = W1; dst = g_W1; N = 256; K = 128; idx = i - 8192; }
    else                { src = W2; dst = g_W2; N = 128; K = 256; idx = i - 16384; }
    int kq = K >> 2;
    int n = idx / kq, k4 = idx % kq;
    float4 o;
    o.x = tf32f(src[(k4 * 4 + 0) * N + n]);
    o.y = tf32f(src[(k4 * 4 + 1) * N + n]);
    o.z = tf32f(src[(k4 * 4 + 2) * N + n]);
    o.w = tf32f(src[(k4 * 4 + 3) * N + n]);
    *reinterpret_cast<float4*>(&dst[n * K + k4 * 4]) = o;
}

// ---------------------------------------------------------------------------
// Kernel A: ret = LayerNorm(gelu(gelu(X@W1+b1)@W2+b2) + X)
// 512 thr = 16 warps (4M x 4N), CTA tile 128 tokens, H in 4 chunks of 64.
// W2C double-buffered; weight staging via cp.async overlapped with GEMM2.
// ---------------------------------------------------------------------------
#define FA_X     0                     // 128*132*4 = 67584
#define FA_W1C   67584                 // 64*132*4  = 33792
#define FA_W2C0  101376                // 128*68*4  = 34816
#define FA_W2C1  136192                // 34816
#define FA_H     171008                // 34816
#define FA_B1    205824                // 1024
#define FA_B2    206848                // 512
#define FA_G     207360                // 512
#define FA_BE    207872                // 512
#define FA_PS    208384                // 4096
#define FA_SZ    212480

__global__ __launch_bounds__(512, 1)
void fused_main_kernel(const float* __restrict__ src,
                       const float* __restrict__ b1, const float* __restrict__ b2,
                       const float* __restrict__ gamma, const float* __restrict__ beta,
                       float* __restrict__ out_ret)
{
    extern __shared__ char smem[];
    const uint32_t sb = smem_u32(smem);
    float* Xs  = (float*)(smem + FA_X);
    float* Hs  = (float*)(smem + FA_H);
    float* b1s = (float*)(smem + FA_B1);
    float* b2s = (float*)(smem + FA_B2);
    float* gs  = (float*)(smem + FA_G);
    float* bs  = (float*)(smem + FA_BE);
    float2* Ps = (float2*)(smem + FA_PS);

    const int tid = threadIdx.x, lane = tid & 31, wid = tid >> 5;
    const int group = lane >> 2, tq = lane & 3;
    const int wm = wid & 3, wn = wid >> 2;       // 4M x 4N
    const int r0 = wm * 32 + group;

    const int s  = blockIdx.y;
    const int b0 = blockIdx.x * 128;
    const float* Xg = src + ((size_t)s * 2048 + b0) * 128;

    // ---- kick off chunk-0 weight staging (cp.async, pre-rounded bytes) ----
    for (int u = tid; u < 2048; u += 512) {
        int row = u >> 5, k4 = u & 31;
        cp16(sb + FA_W1C + (uint32_t)(row * 132 + k4 * 4) * 4, &g_W1[row * 128 + k4 * 4]);
    }
    for (int u = tid; u < 2048; u += 512) {
        int n = u >> 4, k4 = u & 15;
        cp16(sb + FA_W2C0 + (uint32_t)(n * 68 + k4 * 4) * 4, &g_W2[n * 256 + k4 * 4]);
    }
    CP_COMMIT;

    // ---- stage X (tf32), vectorized, stride 132 ----
    for (int u = tid; u < 4096; u += 512) {
        int row = u >> 5, c4 = u & 31;
        float4 v = reinterpret_cast<const float4*>(Xg + row * 128)[c4];
        float4 t = make_float4(tf32f(v.x), tf32f(v.y), tf32f(v.z), tf32f(v.w));
        *reinterpret_cast<float4*>(&Xs[row * 132 + c4 * 4]) = t;
    }
    if (tid < 256) b1s[tid] = b1[tid];
    if (tid < 128) { b2s[tid] = b2[tid]; gs[tid] = gamma[tid]; bs[tid] = beta[tid]; }
    CP_WAIT0;
    __syncthreads();

    // per-lane LDSM addresses
    const int lm = lane & 15, lh = lane >> 4;            // A: row-in-16, k-half
    const int bn = (lane & 7) + ((lane >> 4) << 3);      // B: n-in-16
    const int bk = ((lane >> 3) & 1) * 16;               // B: k-half bytes
    const uint32_t a1base0 = sb + FA_X + (uint32_t)(wm * 32 + lm) * 528 + lh * 16;
    const uint32_t a1base1 = a1base0 + 16 * 528;
    const uint32_t b1base  = sb + FA_W1C + (uint32_t)(wn * 16 + bn) * 528 + bk;
    const uint32_t a2base0 = sb + FA_H + (uint32_t)(wm * 32 + lm) * 272 + lh * 16;
    const uint32_t a2base1 = a2base0 + 16 * 272;
    const uint32_t b2off   = (uint32_t)(wn * 32 + bn) * 272 + bk;

    float acc2[8][4];
#pragma unroll
    for (int i = 0; i < 8; i++) { acc2[i][0] = acc2[i][1] = acc2[i][2] = acc2[i][3] = 0.f; }

#pragma unroll
    for (int c = 0; c < 4; ++c) {
        // ---- GEMM1: Hc = X @ W1c  (warp 32x16, K=128, 16 ksteps) ----
        float acc1[4][4];
#pragma unroll
        for (int i = 0; i < 4; i++) { acc1[i][0] = acc1[i][1] = acc1[i][2] = acc1[i][3] = 0.f; }
#pragma unroll
        for (int ks = 0; ks < 16; ks++) {
            unsigned A0[4], A1[4], B0[4];
            LDSM4(A0, a1base0 + ks * 32);
            LDSM4(A1, a1base1 + ks * 32);
            LDSM4(B0, b1base + ks * 32);
            mma8(acc1[0], A0, B0);     mma8(acc1[1], A0, B0 + 2);
            mma8(acc1[2], A1, B0);     mma8(acc1[3], A1, B0 + 2);
        }

        // ---- epilogue-1: H = tf32(gelu(acc1 + b1)) ----
#pragma unroll
        for (int mt = 0; mt < 2; mt++) {
#pragma unroll
            for (int nt = 0; nt < 2; nt++) {
                int col = wn * 16 + nt * 8 + 2 * tq;
                int rA = r0 + mt * 16, rB = rA + 8;
                float bi0 = b1s[c * 64 + col], bi1 = b1s[c * 64 + col + 1];
                float* v = acc1[mt * 2 + nt];
                *reinterpret_cast<float2*>(&Hs[rA * 68 + col]) =
                    make_float2(tf32f(gelu_exact(v[0] + bi0)), tf32f(gelu_exact(v[1] + bi1)));
                *reinterpret_cast<float2*>(&Hs[rB * 68 + col]) =
                    make_float2(tf32f(gelu_exact(v[2] + bi0)), tf32f(gelu_exact(v[3] + bi1)));
            }
        }
        __syncthreads();   // Hs visible; all GEMM1 reads of W1C done

        // ---- overlap: stage chunk c+1 weights while GEMM2 runs ----
        if (c < 3) {
            int cn = c + 1;
            uint32_t w2n = sb + ((cn & 1) ? FA_W2C1 : FA_W2C0);
            for (int u = tid; u < 2048; u += 512) {
                int row = u >> 5, k4 = u & 31;
                cp16(sb + FA_W1C + (uint32_t)(row * 132 + k4 * 4) * 4,
                     &g_W1[(cn * 64 + row) * 128 + k4 * 4]);
            }
            for (int u = tid; u < 2048; u += 512) {
                int n = u >> 4, k4 = u & 15;
                cp16(w2n + (uint32_t)(n * 68 + k4 * 4) * 4,
                     &g_W2[n * 256 + cn * 64 + k4 * 4]);
            }
            CP_COMMIT;
        }

        // ---- GEMM2: acc2 += Hc @ W2c (warp 32x32, K=64, 8 ksteps) ----
        const uint32_t w2b = sb + ((c & 1) ? FA_W2C1 : FA_W2C0);
        const uint32_t b2base0 = w2b + b2off;
        const uint32_t b2base1 = b2base0 + 16 * 272;
#pragma unroll
        for (int ks = 0; ks < 8; ks++) {
            unsigned A0[4], A1[4], B0[4], B1[4];
            LDSM4(A0, a2base0 + ks * 32);
            LDSM4(A1, a2base1 + ks * 32);
            LDSM4(B0, b2base0 + ks * 32);
            LDSM4(B1, b2base1 + ks * 32);
            mma8(acc2[0], A0, B0);     mma8(acc2[1], A0, B0 + 2);
            mma8(acc2[2], A0, B1);     mma8(acc2[3], A0, B1 + 2);
            mma8(acc2[4], A1, B0);     mma8(acc2[5], A1, B0 + 2);
            mma8(acc2[6], A1, B1);     mma8(acc2[7], A1, B1 + 2);
        }
        CP_WAIT0;
        __syncthreads();   // GEMM2 done (Hs reusable), next weights landed
    }

    // ---- epilogue-2: r = gelu(acc2+b2)+X ; LayerNorm ; store ----
    float sums[4] = {0, 0, 0, 0}, sqs[4] = {0, 0, 0, 0};
    const float2* Xg2 = (const float2*)Xg;
#pragma unroll
    for (int mt = 0; mt < 2; mt++) {
#pragma unroll
        for (int nt = 0; nt < 4; nt++) {
            int col = wn * 32 + nt * 8 + 2 * tq;
            int rA = r0 + mt * 16, rB = rA + 8;
            float2 xa = Xg2[rA * 64 + (col >> 1)];
            float2 xb = Xg2[rB * 64 + (col >> 1)];
            float* v = acc2[mt * 4 + nt];
            v[0] = gelu_exact(v[0] + b2s[col])     + xa.x;
            v[1] = gelu_exact(v[1] + b2s[col + 1]) + xa.y;
            v[2] = gelu_exact(v[2] + b2s[col])     + xb.x;
            v[3] = gelu_exact(v[3] + b2s[col + 1]) + xb.y;
            sums[mt * 2]     += v[0] + v[1]; sqs[mt * 2]     += v[0] * v[0] + v[1] * v[1];
            sums[mt * 2 + 1] += v[2] + v[3]; sqs[mt * 2 + 1] += v[2] * v[2] + v[3] * v[3];
        }
    }
#pragma unroll
    for (int j = 0; j < 4; j++) {
#pragma unroll
        for (int o = 1; o < 4; o <<= 1) {
            sums[j] += __shfl_xor_sync(0xffffffffu, sums[j], o);
            sqs[j]  += __shfl_xor_sync(0xffffffffu, sqs[j],  o);
        }
    }
    if (tq == 0) {
#pragma unroll
        for (int j = 0; j < 4; j++) Ps[(r0 + j * 8) * 4 + wn] = make_float2(sums[j], sqs[j]);
    }
    __syncthreads();
    float mus[4], rss[4];
#pragma unroll
    for (int j = 0; j < 4; j++) {
        int row = r0 + j * 8;
        float ssum = 0.f, ssq = 0.f;
#pragma unroll
        for (int w = 0; w < 4; w++) { float2 p = Ps[row * 4 + w]; ssum += p.x; ssq += p.y; }
        float mu  = ssum * (1.f / 128.f);
        float var = ssq * (1.f / 128.f) - mu * mu;
        mus[j] = mu; rss[j] = rsqrtf(var + 1e-5f);
    }
    float2* og2 = (float2*)(out_ret + ((size_t)s * 2048 + b0) * 128);
#pragma unroll
    for (int mt = 0; mt < 2; mt++) {
#pragma unroll
        for (int nt = 0; nt < 4; nt++) {
            int col = wn * 32 + nt * 8 + 2 * tq;
            int rA = r0 + mt * 16, rB = rA + 8;
            float* v = acc2[mt * 4 + nt];
            float muA = mus[mt * 2],     rsA = rss[mt * 2];
            float muB = mus[mt * 2 + 1], rsB = rss[mt * 2 + 1];
            og2[rA * 64 + (col >> 1)] =
                make_float2((v[0] - muA) * rsA * gs[col]     + bs[col],
                            (v[1] - muA) * rsA * gs[col + 1] + bs[col + 1]);
            og2[rB * 64 + (col >> 1)] =
                make_float2((v[2] - muB) * rsB * gs[col]     + bs[col],
                            (v[3] - muB) * rsB * gs[col + 1] + bs[col + 1]);
        }
    }
}

// ---------------------------------------------------------------------------
// Kernel B: diffs[s-1] = gelu([X_{s-1} | X_s] @ Wb + bb)
// 512 thr = 16 warps (4M x 4N), warp 32x32, K=256 as 4 quarters of 64,
// Wb quarters double-buffered via cp.async overlapped with MMA.
// ---------------------------------------------------------------------------
#define BB_XP    0                     // 67584
#define BB_XC    67584                 // 67584
#define BB_WH0   135168                // 34816
#define BB_WH1   169984                // 34816
#define BB_BB    204800                // 512
#define BB_SZ    205312

__global__ __launch_bounds__(512, 1)
void bracket_kernel(const float* __restrict__ src,
                    const float* __restrict__ bb,
                    float* __restrict__ out_diffs, float* __restrict__ cond)
{
    extern __shared__ char smem[];
    const uint32_t sb = smem_u32(smem);
    float* Xp  = (float*)(smem + BB_XP);
    float* Xc  = (float*)(smem + BB_XC);
    float* bbs = (float*)(smem + BB_BB);

    const int tid = threadIdx.x, lane = tid & 31, wid = tid >> 5;
    const int group = lane >> 2, tq = lane & 3;
    const int wm = wid & 3, wn = wid >> 2;
    const int r0 = wm * 32 + group;

    const int s  = blockIdx.y + 1;
    const int b0 = blockIdx.x * 128;
    if (blockIdx.x == 0 && blockIdx.y == 0 && tid < 3) cond[tid] = 0.f;

    const float* Xgp = src + ((size_t)(s - 1) * 2048 + b0) * 128;
    const float* Xgc = src + ((size_t)s * 2048 + b0) * 128;

    // ---- kick off quarter-0 Wb staging ----
    for (int u = tid; u < 2048; u += 512) {
        int n = u >> 4, k4 = u & 15;
        cp16(sb + BB_WH0 + (uint32_t)(n * 68 + k4 * 4) * 4, &g_Wb[n * 256 + k4 * 4]);
    }
    CP_COMMIT;

    // stage both X tiles (tf32), stride 132
    for (int u = tid; u < 4096; u += 512) {
        int row = u >> 5, c4 = u & 31;
        float4 vp = reinterpret_cast<const float4*>(Xgp + row * 128)[c4];
        float4 vc = reinterpret_cast<const float4*>(Xgc + row * 128)[c4];
        *reinterpret_cast<float4*>(&Xp[row * 132 + c4 * 4]) =
            make_float4(tf32f(vp.x), tf32f(vp.y), tf32f(vp.z), tf32f(vp.w));
        *reinterpret_cast<float4*>(&Xc[row * 132 + c4 * 4]) =
            make_float4(tf32f(vc.x), tf32f(vc.y), tf32f(vc.z), tf32f(vc.w));
    }
    if (tid < 128) bbs[tid] = bb[tid];
    CP_WAIT0;
    __syncthreads();

    const int lm = lane & 15, lh = lane >> 4;
    const int bn = (lane & 7) + ((lane >> 4) << 3);
    const int bk = ((lane >> 3) & 1) * 16;
    const uint32_t aXP = sb + BB_XP + (uint32_t)(wm * 32 + lm) * 528 + lh * 16;
    const uint32_t aXC = sb + BB_XC + (uint32_t)(wm * 32 + lm) * 528 + lh * 16;
    const uint32_t bWoff = (uint32_t)(wn * 32 + bn) * 272 + bk;

    float acc[8][4];
#pragma unroll
    for (int i = 0; i < 8; i++) { acc[i][0] = acc[i][1] = acc[i][2] = acc[i][3] = 0.f; }

#pragma unroll
    for (int q = 0; q < 4; ++q) {
        // overlap: stage quarter q+1 into the other buffer
        if (q < 3) {
            int qn = q + 1;
            uint32_t whn = sb + ((qn & 1) ? BB_WH1 : BB_WH0);
            for (int u = tid; u < 2048; u += 512) {
                int n = u >> 4, k4 = u & 15;
                cp16(whn + (uint32_t)(n * 68 + k4 * 4) * 4,
                     &g_Wb[n * 256 + qn * 64 + k4 * 4]);
            }
            CP_COMMIT;
        }

        const uint32_t wh  = sb + ((q & 1) ? BB_WH1 : BB_WH0);
        const uint32_t a0b = ((q < 2) ? aXP : aXC) + (uint32_t)(q & 1) * 256;
        const uint32_t a1b = a0b + 16 * 528;
        const uint32_t bW0 = wh + bWoff;
        const uint32_t bW1 = bW0 + 16 * 272;
#pragma unroll
        for (int ks = 0; ks < 8; ks++) {
            unsigned A0[4], A1[4], B0[4], B1[4];
            LDSM4(A0, a0b + ks * 32);
            LDSM4(A1, a1b + ks * 32);
            LDSM4(B0, bW0 + ks * 32);
            LDSM4(B1, bW1 + ks * 32);
            mma8(acc[0], A0, B0);     mma8(acc[1], A0, B0 + 2);
            mma8(acc[2], A0, B1);     mma8(acc[3], A0, B1 + 2);
            mma8(acc[4], A1, B0);     mma8(acc[5], A1, B0 + 2);
            mma8(acc[6], A1, B1);     mma8(acc[7], A1, B1 + 2);
        }
        CP_WAIT0;
        __syncthreads();   // quarter q done everywhere; q+1 weights landed
    }

    // epilogue: gelu(acc + bb) -> diffs
    float2* og2 = (float2*)(out_diffs + ((size_t)(s - 1) * 2048 + b0) * 128);
#pragma unroll
    for (int mt = 0; mt < 2; mt++) {
#pragma unroll
        for (int nt = 0; nt < 4; nt++) {
            int col = wn * 32 + nt * 8 + 2 * tq;
            int rA = r0 + mt * 16, rB = rA + 8;
            float bi0 = bbs[col], bi1 = bbs[col + 1];
            float* v = acc[mt * 4 + nt];
            og2[rA * 64 + (col >> 1)] = make_float2(gelu_exact(v[0] + bi0),
                                                    gelu_exact(v[1] + bi1));
            og2[rB * 64 + (col >> 1)] = make_float2(gelu_exact(v[2] + bi0),
                                                    gelu_exact(v[3] + bi1));
        }
    }
}

// ---------------------------------------------------------------------------
// launcher
// ---------------------------------------------------------------------------
extern "C" void kernel_launch(void* const* d_in, const int* in_sizes, int n_in,
                              void* d_out, int out_size)
{
    const float* src   = (const float*)d_in[0];
    const float* Wb    = (const float*)d_in[1];
    const float* bb    = (const float*)d_in[2];
    const float* W1    = (const float*)d_in[3];
    const float* b1    = (const float*)d_in[4];
    const float* W2    = (const float*)d_in[5];
    const float* b2    = (const float*)d_in[6];
    const float* gamma = (const float*)d_in[7];
    const float* beta  = (const float*)d_in[8];
    float* out = (float*)d_out;

    cudaFuncSetAttribute(fused_main_kernel, cudaFuncAttributeMaxDynamicSharedMemorySize, FA_SZ);
    cudaFuncSetAttribute(bracket_kernel,    cudaFuncAttributeMaxDynamicSharedMemorySize, BB_SZ);

    prep_weights<<<96, 256>>>(Wb, W1, W2);

    dim3 gA(16, 256);
    dim3 gB(16, 255);
    fused_main_kernel<<<gA, 512, FA_SZ>>>(src, b1, b2, gamma, beta, out);
    bracket_kernel<<<gB, 512, BB_SZ>>>(src, bb,
                                       out + RET_ELEMS,
                                       out + RET_ELEMS + DIFF_ELEMS);
}

// round 10
// speedup vs baseline: 1.3551x; 1.0015x over previous
#include <cuda_runtime.h>
#include <cstdint>
#include <math.h>

#define RET_ELEMS (256LL * 2048LL * 128LL)
#define DIFF_ELEMS (255LL * 2048LL * 128LL)

// Pre-transposed, tf32-pre-rounded weights: [n][k] row-major.
__device__ float g_Wb[128 * 256];
__device__ float g_W1[256 * 128];
__device__ float g_W2[128 * 256];

// ---------------------------------------------------------------------------
// helpers
// ---------------------------------------------------------------------------
__device__ __forceinline__ float gelu_exact(float x) {
    return 0.5f * x * (1.0f + erff(x * 0.7071067811865476f));
}
__device__ __forceinline__ unsigned f2tf32(float x) {
    unsigned r; asm("cvt.rna.tf32.f32 %0, %1;" : "=r"(r) : "f"(x)); return r;
}
__device__ __forceinline__ float tf32f(float x) { return __uint_as_float(f2tf32(x)); }

__device__ __forceinline__ uint32_t smem_u32(const void* p) {
    uint32_t a;
    asm("{ .reg .u64 t; cvta.to.shared.u64 t, %1; cvt.u32.u64 %0, t; }" : "=r"(a) : "l"(p));
    return a;
}

__device__ __forceinline__ void mma8(float* d, const unsigned* a, const unsigned* b) {
    asm volatile(
        "mma.sync.aligned.m16n8k8.row.col.f32.tf32.tf32.f32 "
        "{%0,%1,%2,%3}, {%4,%5,%6,%7}, {%8,%9}, {%0,%1,%2,%3};"
        : "+f"(d[0]), "+f"(d[1]), "+f"(d[2]), "+f"(d[3])
        : "r"(a[0]), "r"(a[1]), "r"(a[2]), "r"(a[3]), "r"(b[0]), "r"(b[1]));
}

#define LDSM4(R, addr) \
    asm volatile("ldmatrix.sync.aligned.m8n8.x4.shared.b16 {%0,%1,%2,%3}, [%4];" \
                 : "=r"((R)[0]), "=r"((R)[1]), "=r"((R)[2]), "=r"((R)[3]) : "r"(addr))

__device__ __forceinline__ void cp16(uint32_t dst, const void* src) {
    asm volatile("cp.async.cg.shared.global [%0], [%1], 16;" :: "r"(dst), "l"(src));
}
#define CP_COMMIT asm volatile("cp.async.commit_group;" ::: "memory")
#define CP_WAIT0  asm volatile("cp.async.wait_group 0;"  ::: "memory")

// ---------------------------------------------------------------------------
// prep: transpose + tf32-round weights into __device__ scratch
// ---------------------------------------------------------------------------
__global__ void prep_weights(const float* __restrict__ Wb,
                             const float* __restrict__ W1,
                             const float* __restrict__ W2)
{
    int i = blockIdx.x * 256 + threadIdx.x;       // 0 .. 24575 float4 slots
    const float* src; float* dst; int N, K, idx;
    if (i < 8192)       { src = Wb; dst = g_Wb; N = 128; K = 256; idx = i; }
    else if (i < 16384) { src = W1; dst = g_W1; N = 256; K = 128; idx = i - 8192; }
    else                { src = W2; dst = g_W2; N = 128; K = 256; idx = i - 16384; }
    int kq = K >> 2;
    int n = idx / kq, k4 = idx % kq;
    float4 o;
    o.x = tf32f(src[(k4 * 4 + 0) * N + n]);
    o.y = tf32f(src[(k4 * 4 + 1) * N + n]);
    o.z = tf32f(src[(k4 * 4 + 2) * N + n]);
    o.w = tf32f(src[(k4 * 4 + 3) * N + n]);
    *reinterpret_cast<float4*>(&dst[n * K + k4 * 4]) = o;
}

// ---------------------------------------------------------------------------
// Kernel A: ret = LayerNorm(gelu(gelu(X@W1+b1)@W2+b2) + X)
// 512 thr = 16 warps (4M x 4N), CTA tile 128 tokens, H in 4 chunks of 64.
// W2C double-buffered via cp.async; LDSM fragments software-pipelined.
// ---------------------------------------------------------------------------
#define FA_X     0                     // 128*132*4 = 67584
#define FA_W1C   67584                 // 64*132*4  = 33792
#define FA_W2C0  101376                // 128*68*4  = 34816
#define FA_W2C1  136192                // 34816
#define FA_H     171008                // 34816
#define FA_B1    205824                // 1024
#define FA_B2    206848                // 512
#define FA_G     207360                // 512
#define FA_BE    207872                // 512
#define FA_PS    208384                // 4096
#define FA_SZ    212480

__global__ __launch_bounds__(512, 1)
void fused_main_kernel(const float* __restrict__ src,
                       const float* __restrict__ b1, const float* __restrict__ b2,
                       const float* __restrict__ gamma, const float* __restrict__ beta,
                       float* __restrict__ out_ret)
{
    extern __shared__ char smem[];
    const uint32_t sb = smem_u32(smem);
    float* Xs  = (float*)(smem + FA_X);
    float* Hs  = (float*)(smem + FA_H);
    float* b1s = (float*)(smem + FA_B1);
    float* b2s = (float*)(smem + FA_B2);
    float* gs  = (float*)(smem + FA_G);
    float* bs  = (float*)(smem + FA_BE);
    float2* Ps = (float2*)(smem + FA_PS);

    const int tid = threadIdx.x, lane = tid & 31, wid = tid >> 5;
    const int group = lane >> 2, tq = lane & 3;
    const int wm = wid & 3, wn = wid >> 2;       // 4M x 4N
    const int r0 = wm * 32 + group;

    const int s  = blockIdx.y;
    const int b0 = blockIdx.x * 128;
    const float* Xg = src + ((size_t)s * 2048 + b0) * 128;

    // ---- kick off chunk-0 weight staging ----
    for (int u = tid; u < 2048; u += 512) {
        int row = u >> 5, k4 = u & 31;
        cp16(sb + FA_W1C + (uint32_t)(row * 132 + k4 * 4) * 4, &g_W1[row * 128 + k4 * 4]);
    }
    for (int u = tid; u < 2048; u += 512) {
        int n = u >> 4, k4 = u & 15;
        cp16(sb + FA_W2C0 + (uint32_t)(n * 68 + k4 * 4) * 4, &g_W2[n * 256 + k4 * 4]);
    }
    CP_COMMIT;

    // ---- stage X (tf32), vectorized, stride 132 ----
    for (int u = tid; u < 4096; u += 512) {
        int row = u >> 5, c4 = u & 31;
        float4 v = reinterpret_cast<const float4*>(Xg + row * 128)[c4];
        float4 t = make_float4(tf32f(v.x), tf32f(v.y), tf32f(v.z), tf32f(v.w));
        *reinterpret_cast<float4*>(&Xs[row * 132 + c4 * 4]) = t;
    }
    if (tid < 256) b1s[tid] = b1[tid];
    if (tid < 128) { b2s[tid] = b2[tid]; gs[tid] = gamma[tid]; bs[tid] = beta[tid]; }
    CP_WAIT0;
    __syncthreads();

    // per-lane LDSM addresses
    const int lm = lane & 15, lh = lane >> 4;            // A: row-in-16, k-half
    const int bn = (lane & 7) + ((lane >> 4) << 3);      // B: n-in-16
    const int bk = ((lane >> 3) & 1) * 16;               // B: k-half bytes
    const uint32_t a1base0 = sb + FA_X + (uint32_t)(wm * 32 + lm) * 528 + lh * 16;
    const uint32_t a1base1 = a1base0 + 16 * 528;
    const uint32_t b1base  = sb + FA_W1C + (uint32_t)(wn * 16 + bn) * 528 + bk;
    const uint32_t a2base0 = sb + FA_H + (uint32_t)(wm * 32 + lm) * 272 + lh * 16;
    const uint32_t a2base1 = a2base0 + 16 * 272;
    const uint32_t b2off   = (uint32_t)(wn * 32 + bn) * 272 + bk;

    float acc2[8][4];
#pragma unroll
    for (int i = 0; i < 8; i++) { acc2[i][0] = acc2[i][1] = acc2[i][2] = acc2[i][3] = 0.f; }

#pragma unroll
    for (int c = 0; c < 4; ++c) {
        // ---- GEMM1: Hc = X @ W1c (warp 32x16, K=128, 16 ksteps, pipelined) ----
        float acc1[4][4];
#pragma unroll
        for (int i = 0; i < 4; i++) { acc1[i][0] = acc1[i][1] = acc1[i][2] = acc1[i][3] = 0.f; }
        {
            unsigned A0[2][4], A1[2][4], B0[2][4];
            LDSM4(A0[0], a1base0);
            LDSM4(A1[0], a1base1);
            LDSM4(B0[0], b1base);
#pragma unroll
            for (int ks = 0; ks < 16; ks++) {
                int cur = ks & 1, nxt = cur ^ 1;
                if (ks < 15) {
                    LDSM4(A0[nxt], a1base0 + (ks + 1) * 32);
                    LDSM4(A1[nxt], a1base1 + (ks + 1) * 32);
                    LDSM4(B0[nxt], b1base  + (ks + 1) * 32);
                }
                mma8(acc1[0], A0[cur], B0[cur]);  mma8(acc1[1], A0[cur], B0[cur] + 2);
                mma8(acc1[2], A1[cur], B0[cur]);  mma8(acc1[3], A1[cur], B0[cur] + 2);
            }
        }

        // ---- epilogue-1: H = tf32(gelu(acc1 + b1)) ----
#pragma unroll
        for (int mt = 0; mt < 2; mt++) {
#pragma unroll
            for (int nt = 0; nt < 2; nt++) {
                int col = wn * 16 + nt * 8 + 2 * tq;
                int rA = r0 + mt * 16, rB = rA + 8;
                float bi0 = b1s[c * 64 + col], bi1 = b1s[c * 64 + col + 1];
                float* v = acc1[mt * 2 + nt];
                *reinterpret_cast<float2*>(&Hs[rA * 68 + col]) =
                    make_float2(tf32f(gelu_exact(v[0] + bi0)), tf32f(gelu_exact(v[1] + bi1)));
                *reinterpret_cast<float2*>(&Hs[rB * 68 + col]) =
                    make_float2(tf32f(gelu_exact(v[2] + bi0)), tf32f(gelu_exact(v[3] + bi1)));
            }
        }
        __syncthreads();   // Hs visible; all GEMM1 reads of W1C done

        // ---- overlap: stage chunk c+1 weights while GEMM2 runs ----
        if (c < 3) {
            int cn = c + 1;
            uint32_t w2n = sb + ((cn & 1) ? FA_W2C1 : FA_W2C0);
            for (int u = tid; u < 2048; u += 512) {
                int row = u >> 5, k4 = u & 31;
                cp16(sb + FA_W1C + (uint32_t)(row * 132 + k4 * 4) * 4,
                     &g_W1[(cn * 64 + row) * 128 + k4 * 4]);
            }
            for (int u = tid; u < 2048; u += 512) {
                int n = u >> 4, k4 = u & 15;
                cp16(w2n + (uint32_t)(n * 68 + k4 * 4) * 4,
                     &g_W2[n * 256 + cn * 64 + k4 * 4]);
            }
            CP_COMMIT;
        }

        // ---- GEMM2: acc2 += Hc @ W2c (warp 32x32, K=64, 8 ksteps, pipelined) ----
        {
            const uint32_t w2b = sb + ((c & 1) ? FA_W2C1 : FA_W2C0);
            const uint32_t b2base0 = w2b + b2off;
            const uint32_t b2base1 = b2base0 + 16 * 272;
            unsigned A0[2][4], A1[2][4], B0[2][4], B1[2][4];
            LDSM4(A0[0], a2base0);
            LDSM4(A1[0], a2base1);
            LDSM4(B0[0], b2base0);
            LDSM4(B1[0], b2base1);
#pragma unroll
            for (int ks = 0; ks < 8; ks++) {
                int cur = ks & 1, nxt = cur ^ 1;
                if (ks < 7) {
                    LDSM4(A0[nxt], a2base0 + (ks + 1) * 32);
                    LDSM4(A1[nxt], a2base1 + (ks + 1) * 32);
                    LDSM4(B0[nxt], b2base0 + (ks + 1) * 32);
                    LDSM4(B1[nxt], b2base1 + (ks + 1) * 32);
                }
                mma8(acc2[0], A0[cur], B0[cur]);  mma8(acc2[1], A0[cur], B0[cur] + 2);
                mma8(acc2[2], A0[cur], B1[cur]);  mma8(acc2[3], A0[cur], B1[cur] + 2);
                mma8(acc2[4], A1[cur], B0[cur]);  mma8(acc2[5], A1[cur], B0[cur] + 2);
                mma8(acc2[6], A1[cur], B1[cur]);  mma8(acc2[7], A1[cur], B1[cur] + 2);
            }
        }
        CP_WAIT0;
        __syncthreads();   // GEMM2 done (Hs reusable), next weights landed
    }

    // ---- epilogue-2: r = gelu(acc2+b2)+X ; LayerNorm ; store ----
    float sums[4] = {0, 0, 0, 0}, sqs[4] = {0, 0, 0, 0};
    const float2* Xg2 = (const float2*)Xg;
#pragma unroll
    for (int mt = 0; mt < 2; mt++) {
#pragma unroll
        for (int nt = 0; nt < 4; nt++) {
            int col = wn * 32 + nt * 8 + 2 * tq;
            int rA = r0 + mt * 16, rB = rA + 8;
            float2 xa = Xg2[rA * 64 + (col >> 1)];
            float2 xb = Xg2[rB * 64 + (col >> 1)];
            float* v = acc2[mt * 4 + nt];
            v[0] = gelu_exact(v[0] + b2s[col])     + xa.x;
            v[1] = gelu_exact(v[1] + b2s[col + 1]) + xa.y;
            v[2] = gelu_exact(v[2] + b2s[col])     + xb.x;
            v[3] = gelu_exact(v[3] + b2s[col + 1]) + xb.y;
            sums[mt * 2]     += v[0] + v[1]; sqs[mt * 2]     += v[0] * v[0] + v[1] * v[1];
            sums[mt * 2 + 1] += v[2] + v[3]; sqs[mt * 2 + 1] += v[2] * v[2] + v[3] * v[3];
        }
    }
#pragma unroll
    for (int j = 0; j < 4; j++) {
#pragma unroll
        for (int o = 1; o < 4; o <<= 1) {
            sums[j] += __shfl_xor_sync(0xffffffffu, sums[j], o);
            sqs[j]  += __shfl_xor_sync(0xffffffffu, sqs[j],  o);
        }
    }
    if (tq == 0) {
#pragma unroll
        for (int j = 0; j < 4; j++) Ps[(r0 + j * 8) * 4 + wn] = make_float2(sums[j], sqs[j]);
    }
    __syncthreads();
    float mus[4], rss[4];
#pragma unroll
    for (int j = 0; j < 4; j++) {
        int row = r0 + j * 8;
        float ssum = 0.f, ssq = 0.f;
#pragma unroll
        for (int w = 0; w < 4; w++) { float2 p = Ps[row * 4 + w]; ssum += p.x; ssq += p.y; }
        float mu  = ssum * (1.f / 128.f);
        float var = ssq * (1.f / 128.f) - mu * mu;
        mus[j] = mu; rss[j] = rsqrtf(var + 1e-5f);
    }
    float2* og2 = (float2*)(out_ret + ((size_t)s * 2048 + b0) * 128);
#pragma unroll
    for (int mt = 0; mt < 2; mt++) {
#pragma unroll
        for (int nt = 0; nt < 4; nt++) {
            int col = wn * 32 + nt * 8 + 2 * tq;
            int rA = r0 + mt * 16, rB = rA + 8;
            float* v = acc2[mt * 4 + nt];
            float muA = mus[mt * 2],     rsA = rss[mt * 2];
            float muB = mus[mt * 2 + 1], rsB = rss[mt * 2 + 1];
            og2[rA * 64 + (col >> 1)] =
                make_float2((v[0] - muA) * rsA * gs[col]     + bs[col],
                            (v[1] - muA) * rsA * gs[col + 1] + bs[col + 1]);
            og2[rB * 64 + (col >> 1)] =
                make_float2((v[2] - muB) * rsB * gs[col]     + bs[col],
                            (v[3] - muB) * rsB * gs[col + 1] + bs[col + 1]);
        }
    }
}

// ---------------------------------------------------------------------------
// Kernel B: diffs[s-1] = gelu([X_{s-1} | X_s] @ Wb + bb)
// 512 thr = 16 warps (4M x 4N), warp 32x32, K=256 as 4 quarters of 64,
// Wb quarters double-buffered via cp.async; LDSM fragments pipelined.
// ---------------------------------------------------------------------------
#define BB_XP    0                     // 67584
#define BB_XC    67584                 // 67584
#define BB_WH0   135168                // 34816
#define BB_WH1   169984                // 34816
#define BB_BB    204800                // 512
#define BB_SZ    205312

__global__ __launch_bounds__(512, 1)
void bracket_kernel(const float* __restrict__ src,
                    const float* __restrict__ bb,
                    float* __restrict__ out_diffs, float* __restrict__ cond)
{
    extern __shared__ char smem[];
    const uint32_t sb = smem_u32(smem);
    float* Xp  = (float*)(smem + BB_XP);
    float* Xc  = (float*)(smem + BB_XC);
    float* bbs = (float*)(smem + BB_BB);

    const int tid = threadIdx.x, lane = tid & 31, wid = tid >> 5;
    const int group = lane >> 2, tq = lane & 3;
    const int wm = wid & 3, wn = wid >> 2;
    const int r0 = wm * 32 + group;

    const int s  = blockIdx.y + 1;
    const int b0 = blockIdx.x * 128;
    if (blockIdx.x == 0 && blockIdx.y == 0 && tid < 3) cond[tid] = 0.f;

    const float* Xgp = src + ((size_t)(s - 1) * 2048 + b0) * 128;
    const float* Xgc = src + ((size_t)s * 2048 + b0) * 128;

    // ---- kick off quarter-0 Wb staging ----
    for (int u = tid; u < 2048; u += 512) {
        int n = u >> 4, k4 = u & 15;
        cp16(sb + BB_WH0 + (uint32_t)(n * 68 + k4 * 4) * 4, &g_Wb[n * 256 + k4 * 4]);
    }
    CP_COMMIT;

    // stage both X tiles (tf32), stride 132
    for (int u = tid; u < 4096; u += 512) {
        int row = u >> 5, c4 = u & 31;
        float4 vp = reinterpret_cast<const float4*>(Xgp + row * 128)[c4];
        float4 vc = reinterpret_cast<const float4*>(Xgc + row * 128)[c4];
        *reinterpret_cast<float4*>(&Xp[row * 132 + c4 * 4]) =
            make_float4(tf32f(vp.x), tf32f(vp.y), tf32f(vp.z), tf32f(vp.w));
        *reinterpret_cast<float4*>(&Xc[row * 132 + c4 * 4]) =
            make_float4(tf32f(vc.x), tf32f(vc.y), tf32f(vc.z), tf32f(vc.w));
    }
    if (tid < 128) bbs[tid] = bb[tid];
    CP_WAIT0;
    __syncthreads();

    const int lm = lane & 15, lh = lane >> 4;
    const int bn = (lane & 7) + ((lane >> 4) << 3);
    const int bk = ((lane >> 3) & 1) * 16;
    const uint32_t aXP = sb + BB_XP + (uint32_t)(wm * 32 + lm) * 528 + lh * 16;
    const uint32_t aXC = sb + BB_XC + (uint32_t)(wm * 32 + lm) * 528 + lh * 16;
    const uint32_t bWoff = (uint32_t)(wn * 32 + bn) * 272 + bk;

    float acc[8][4];
#pragma unroll
    for (int i = 0; i < 8; i++) { acc[i][0] = acc[i][1] = acc[i][2] = acc[i][3] = 0.f; }

#pragma unroll
    for (int q = 0; q < 4; ++q) {
        // overlap: stage quarter q+1 into the other buffer
        if (q < 3) {
            int qn = q + 1;
            uint32_t whn = sb + ((qn & 1) ? BB_WH1 : BB_WH0);
            for (int u = tid; u < 2048; u += 512) {
                int n = u >> 4, k4 = u & 15;
                cp16(whn + (uint32_t)(n * 68 + k4 * 4) * 4,
                     &g_Wb[n * 256 + qn * 64 + k4 * 4]);
            }
            CP_COMMIT;
        }

        const uint32_t wh  = sb + ((q & 1) ? BB_WH1 : BB_WH0);
        const uint32_t a0b = ((q < 2) ? aXP : aXC) + (uint32_t)(q & 1) * 256;
        const uint32_t a1b = a0b + 16 * 528;
        const uint32_t bW0 = wh + bWoff;
        const uint32_t bW1 = bW0 + 16 * 272;

        unsigned A0[2][4], A1[2][4], B0[2][4], B1[2][4];
        LDSM4(A0[0], a0b);
        LDSM4(A1[0], a1b);
        LDSM4(B0[0], bW0);
        LDSM4(B1[0], bW1);
#pragma unroll
        for (int ks = 0; ks < 8; ks++) {
            int cur = ks & 1, nxt = cur ^ 1;
            if (ks < 7) {
                LDSM4(A0[nxt], a0b + (ks + 1) * 32);
                LDSM4(A1[nxt], a1b + (ks + 1) * 32);
                LDSM4(B0[nxt], bW0 + (ks + 1) * 32);
                LDSM4(B1[nxt], bW1 + (ks + 1) * 32);
            }
            mma8(acc[0], A0[cur], B0[cur]);  mma8(acc[1], A0[cur], B0[cur] + 2);
            mma8(acc[2], A0[cur], B1[cur]);  mma8(acc[3], A0[cur], B1[cur] + 2);
            mma8(acc[4], A1[cur], B0[cur]);  mma8(acc[5], A1[cur], B0[cur] + 2);
            mma8(acc[6], A1[cur], B1[cur]);  mma8(acc[7], A1[cur], B1[cur] + 2);
        }
        CP_WAIT0;
        __syncthreads();   // quarter q done everywhere; q+1 weights landed
    }

    // epilogue: gelu(acc + bb) -> diffs
    float2* og2 = (float2*)(out_diffs + ((size_t)(s - 1) * 2048 + b0) * 128);
#pragma unroll
    for (int mt = 0; mt < 2; mt++) {
#pragma unroll
        for (int nt = 0; nt < 4; nt++) {
            int col = wn * 32 + nt * 8 + 2 * tq;
            int rA = r0 + mt * 16, rB = rA + 8;
            float bi0 = bbs[col], bi1 = bbs[col + 1];
            float* v = acc[mt * 4 + nt];
            og2[rA * 64 + (col >> 1)] = make_float2(gelu_exact(v[0] + bi0),
                                                    gelu_exact(v[1] + bi1));
            og2[rB * 64 + (col >> 1)] = make_float2(gelu_exact(v[2] + bi0),
                                                    gelu_exact(v[3] + bi1));
        }
    }
}

// ---------------------------------------------------------------------------
// launcher
// ---------------------------------------------------------------------------
extern "C" void kernel_launch(void* const* d_in, const int* in_sizes, int n_in,
                              void* d_out, int out_size)
{
    const float* src   = (const float*)d_in[0];
    const float* Wb    = (const float*)d_in[1];
    const float* bb    = (const float*)d_in[2];
    const float* W1    = (const float*)d_in[3];
    const float* b1    = (const float*)d_in[4];
    const float* W2    = (const float*)d_in[5];
    const float* b2    = (const float*)d_in[6];
    const float* gamma = (const float*)d_in[7];
    const float* beta  = (const float*)d_in[8];
    float* out = (float*)d_out;

    cudaFuncSetAttribute(fused_main_kernel, cudaFuncAttributeMaxDynamicSharedMemorySize, FA_SZ);
    cudaFuncSetAttribute(bracket_kernel,    cudaFuncAttributeMaxDynamicSharedMemorySize, BB_SZ);

    prep_weights<<<96, 256>>>(Wb, W1, W2);

    dim3 gA(16, 256);
    dim3 gB(16, 255);
    fused_main_kernel<<<gA, 512, FA_SZ>>>(src, b1, b2, gamma, beta, out);
    bracket_kernel<<<gB, 512, BB_SZ>>>(src, bb,
                                       out + RET_ELEMS,
                                       out + RET_ELEMS + DIFF_ELEMS);
}

// round 11
// speedup vs baseline: 1.4389x; 1.0619x over previous
#include <cuda_runtime.h>
#include <cstdint>
#include <math.h>

#define RET_ELEMS (256LL * 2048LL * 128LL)
#define DIFF_ELEMS (255LL * 2048LL * 128LL)

// Pre-transposed, tf32-pre-rounded weights: [n][k] row-major.
__device__ float g_Wb[128 * 256];
__device__ float g_W1[256 * 128];
__device__ float g_W2[128 * 256];

// ---------------------------------------------------------------------------
// helpers
// ---------------------------------------------------------------------------
__device__ __forceinline__ float gelu_exact(float x) {
    return 0.5f * x * (1.0f + erff(x * 0.7071067811865476f));
}
__device__ __forceinline__ unsigned f2tf32(float x) {
    unsigned r; asm("cvt.rna.tf32.f32 %0, %1;" : "=r"(r) : "f"(x)); return r;
}
__device__ __forceinline__ float tf32f(float x) { return __uint_as_float(f2tf32(x)); }

__device__ __forceinline__ uint32_t smem_u32(const void* p) {
    uint32_t a;
    asm("{ .reg .u64 t; cvta.to.shared.u64 t, %1; cvt.u32.u64 %0, t; }" : "=r"(a) : "l"(p));
    return a;
}

__device__ __forceinline__ void mma8(float* d, const unsigned* a, const unsigned* b) {
    asm volatile(
        "mma.sync.aligned.m16n8k8.row.col.f32.tf32.tf32.f32 "
        "{%0,%1,%2,%3}, {%4,%5,%6,%7}, {%8,%9}, {%0,%1,%2,%3};"
        : "+f"(d[0]), "+f"(d[1]), "+f"(d[2]), "+f"(d[3])
        : "r"(a[0]), "r"(a[1]), "r"(a[2]), "r"(a[3]), "r"(b[0]), "r"(b[1]));
}

#define LDSM4(R, addr) \
    asm volatile("ldmatrix.sync.aligned.m8n8.x4.shared.b16 {%0,%1,%2,%3}, [%4];" \
                 : "=r"((R)[0]), "=r"((R)[1]), "=r"((R)[2]), "=r"((R)[3]) : "r"(addr))

__device__ __forceinline__ void cp16(uint32_t dst, const void* src) {
    asm volatile("cp.async.cg.shared.global [%0], [%1], 16;" :: "r"(dst), "l"(src));
}
#define CP_COMMIT asm volatile("cp.async.commit_group;" ::: "memory")
#define CP_WAIT0  asm volatile("cp.async.wait_group 0;"  ::: "memory")

// ---------------------------------------------------------------------------
// prep: transpose + tf32-round weights into __device__ scratch
// ---------------------------------------------------------------------------
__global__ void prep_weights(const float* __restrict__ Wb,
                             const float* __restrict__ W1,
                             const float* __restrict__ W2)
{
    int i = blockIdx.x * 256 + threadIdx.x;       // 0 .. 24575 float4 slots
    const float* src; float* dst; int N, K, idx;
    if (i < 8192)       { src = Wb; dst = g_Wb; N = 128; K = 256; idx = i; }
    else if (i < 16384) { src = W1; dst = g_W1; N = 256; K = 128; idx = i - 8192; }
    else                { src = W2; dst = g_W2; N = 128; K = 256; idx = i - 16384; }
    int kq = K >> 2;
    int n = idx / kq, k4 = idx % kq;
    float4 o;
    o.x = tf32f(src[(k4 * 4 + 0) * N + n]);
    o.y = tf32f(src[(k4 * 4 + 1) * N + n]);
    o.z = tf32f(src[(k4 * 4 + 2) * N + n]);
    o.w = tf32f(src[(k4 * 4 + 3) * N + n]);
    *reinterpret_cast<float4*>(&dst[n * K + k4 * 4]) = o;
}

// ---------------------------------------------------------------------------
// Kernel A: ret = LayerNorm(gelu(gelu(X@W1+b1)@W2+b2) + X)   (unchanged R10)
// ---------------------------------------------------------------------------
#define FA_X     0
#define FA_W1C   67584
#define FA_W2C0  101376
#define FA_W2C1  136192
#define FA_H     171008
#define FA_B1    205824
#define FA_B2    206848
#define FA_G     207360
#define FA_BE    207872
#define FA_PS    208384
#define FA_SZ    212480

__global__ __launch_bounds__(512, 1)
void fused_main_kernel(const float* __restrict__ src,
                       const float* __restrict__ b1, const float* __restrict__ b2,
                       const float* __restrict__ gamma, const float* __restrict__ beta,
                       float* __restrict__ out_ret)
{
    extern __shared__ char smem[];
    const uint32_t sb = smem_u32(smem);
    float* Xs  = (float*)(smem + FA_X);
    float* Hs  = (float*)(smem + FA_H);
    float* b1s = (float*)(smem + FA_B1);
    float* b2s = (float*)(smem + FA_B2);
    float* gs  = (float*)(smem + FA_G);
    float* bs  = (float*)(smem + FA_BE);
    float2* Ps = (float2*)(smem + FA_PS);

    const int tid = threadIdx.x, lane = tid & 31, wid = tid >> 5;
    const int group = lane >> 2, tq = lane & 3;
    const int wm = wid & 3, wn = wid >> 2;
    const int r0 = wm * 32 + group;

    const int s  = blockIdx.y;
    const int b0 = blockIdx.x * 128;
    const float* Xg = src + ((size_t)s * 2048 + b0) * 128;

    for (int u = tid; u < 2048; u += 512) {
        int row = u >> 5, k4 = u & 31;
        cp16(sb + FA_W1C + (uint32_t)(row * 132 + k4 * 4) * 4, &g_W1[row * 128 + k4 * 4]);
    }
    for (int u = tid; u < 2048; u += 512) {
        int n = u >> 4, k4 = u & 15;
        cp16(sb + FA_W2C0 + (uint32_t)(n * 68 + k4 * 4) * 4, &g_W2[n * 256 + k4 * 4]);
    }
    CP_COMMIT;

    for (int u = tid; u < 4096; u += 512) {
        int row = u >> 5, c4 = u & 31;
        float4 v = reinterpret_cast<const float4*>(Xg + row * 128)[c4];
        float4 t = make_float4(tf32f(v.x), tf32f(v.y), tf32f(v.z), tf32f(v.w));
        *reinterpret_cast<float4*>(&Xs[row * 132 + c4 * 4]) = t;
    }
    if (tid < 256) b1s[tid] = b1[tid];
    if (tid < 128) { b2s[tid] = b2[tid]; gs[tid] = gamma[tid]; bs[tid] = beta[tid]; }
    CP_WAIT0;
    __syncthreads();

    const int lm = lane & 15, lh = lane >> 4;
    const int bn = (lane & 7) + ((lane >> 4) << 3);
    const int bk = ((lane >> 3) & 1) * 16;
    const uint32_t a1base0 = sb + FA_X + (uint32_t)(wm * 32 + lm) * 528 + lh * 16;
    const uint32_t a1base1 = a1base0 + 16 * 528;
    const uint32_t b1base  = sb + FA_W1C + (uint32_t)(wn * 16 + bn) * 528 + bk;
    const uint32_t a2base0 = sb + FA_H + (uint32_t)(wm * 32 + lm) * 272 + lh * 16;
    const uint32_t a2base1 = a2base0 + 16 * 272;
    const uint32_t b2off   = (uint32_t)(wn * 32 + bn) * 272 + bk;

    float acc2[8][4];
#pragma unroll
    for (int i = 0; i < 8; i++) { acc2[i][0] = acc2[i][1] = acc2[i][2] = acc2[i][3] = 0.f; }

#pragma unroll
    for (int c = 0; c < 4; ++c) {
        float acc1[4][4];
#pragma unroll
        for (int i = 0; i < 4; i++) { acc1[i][0] = acc1[i][1] = acc1[i][2] = acc1[i][3] = 0.f; }
        {
            unsigned A0[2][4], A1[2][4], B0[2][4];
            LDSM4(A0[0], a1base0);
            LDSM4(A1[0], a1base1);
            LDSM4(B0[0], b1base);
#pragma unroll
            for (int ks = 0; ks < 16; ks++) {
                int cur = ks & 1, nxt = cur ^ 1;
                if (ks < 15) {
                    LDSM4(A0[nxt], a1base0 + (ks + 1) * 32);
                    LDSM4(A1[nxt], a1base1 + (ks + 1) * 32);
                    LDSM4(B0[nxt], b1base  + (ks + 1) * 32);
                }
                mma8(acc1[0], A0[cur], B0[cur]);  mma8(acc1[1], A0[cur], B0[cur] + 2);
                mma8(acc1[2], A1[cur], B0[cur]);  mma8(acc1[3], A1[cur], B0[cur] + 2);
            }
        }

#pragma unroll
        for (int mt = 0; mt < 2; mt++) {
#pragma unroll
            for (int nt = 0; nt < 2; nt++) {
                int col = wn * 16 + nt * 8 + 2 * tq;
                int rA = r0 + mt * 16, rB = rA + 8;
                float bi0 = b1s[c * 64 + col], bi1 = b1s[c * 64 + col + 1];
                float* v = acc1[mt * 2 + nt];
                *reinterpret_cast<float2*>(&Hs[rA * 68 + col]) =
                    make_float2(tf32f(gelu_exact(v[0] + bi0)), tf32f(gelu_exact(v[1] + bi1)));
                *reinterpret_cast<float2*>(&Hs[rB * 68 + col]) =
                    make_float2(tf32f(gelu_exact(v[2] + bi0)), tf32f(gelu_exact(v[3] + bi1)));
            }
        }
        __syncthreads();

        if (c < 3) {
            int cn = c + 1;
            uint32_t w2n = sb + ((cn & 1) ? FA_W2C1 : FA_W2C0);
            for (int u = tid; u < 2048; u += 512) {
                int row = u >> 5, k4 = u & 31;
                cp16(sb + FA_W1C + (uint32_t)(row * 132 + k4 * 4) * 4,
                     &g_W1[(cn * 64 + row) * 128 + k4 * 4]);
            }
            for (int u = tid; u < 2048; u += 512) {
                int n = u >> 4, k4 = u & 15;
                cp16(w2n + (uint32_t)(n * 68 + k4 * 4) * 4,
                     &g_W2[n * 256 + cn * 64 + k4 * 4]);
            }
            CP_COMMIT;
        }

        {
            const uint32_t w2b = sb + ((c & 1) ? FA_W2C1 : FA_W2C0);
            const uint32_t b2base0 = w2b + b2off;
            const uint32_t b2base1 = b2base0 + 16 * 272;
            unsigned A0[2][4], A1[2][4], B0[2][4], B1[2][4];
            LDSM4(A0[0], a2base0);
            LDSM4(A1[0], a2base1);
            LDSM4(B0[0], b2base0);
            LDSM4(B1[0], b2base1);
#pragma unroll
            for (int ks = 0; ks < 8; ks++) {
                int cur = ks & 1, nxt = cur ^ 1;
                if (ks < 7) {
                    LDSM4(A0[nxt], a2base0 + (ks + 1) * 32);
                    LDSM4(A1[nxt], a2base1 + (ks + 1) * 32);
                    LDSM4(B0[nxt], b2base0 + (ks + 1) * 32);
                    LDSM4(B1[nxt], b2base1 + (ks + 1) * 32);
                }
                mma8(acc2[0], A0[cur], B0[cur]);  mma8(acc2[1], A0[cur], B0[cur] + 2);
                mma8(acc2[2], A0[cur], B1[cur]);  mma8(acc2[3], A0[cur], B1[cur] + 2);
                mma8(acc2[4], A1[cur], B0[cur]);  mma8(acc2[5], A1[cur], B0[cur] + 2);
                mma8(acc2[6], A1[cur], B1[cur]);  mma8(acc2[7], A1[cur], B1[cur] + 2);
            }
        }
        CP_WAIT0;
        __syncthreads();
    }

    float sums[4] = {0, 0, 0, 0}, sqs[4] = {0, 0, 0, 0};
    const float2* Xg2 = (const float2*)Xg;
#pragma unroll
    for (int mt = 0; mt < 2; mt++) {
#pragma unroll
        for (int nt = 0; nt < 4; nt++) {
            int col = wn * 32 + nt * 8 + 2 * tq;
            int rA = r0 + mt * 16, rB = rA + 8;
            float2 xa = Xg2[rA * 64 + (col >> 1)];
            float2 xb = Xg2[rB * 64 + (col >> 1)];
            float* v = acc2[mt * 4 + nt];
            v[0] = gelu_exact(v[0] + b2s[col])     + xa.x;
            v[1] = gelu_exact(v[1] + b2s[col + 1]) + xa.y;
            v[2] = gelu_exact(v[2] + b2s[col])     + xb.x;
            v[3] = gelu_exact(v[3] + b2s[col + 1]) + xb.y;
            sums[mt * 2]     += v[0] + v[1]; sqs[mt * 2]     += v[0] * v[0] + v[1] * v[1];
            sums[mt * 2 + 1] += v[2] + v[3]; sqs[mt * 2 + 1] += v[2] * v[2] + v[3] * v[3];
        }
    }
#pragma unroll
    for (int j = 0; j < 4; j++) {
#pragma unroll
        for (int o = 1; o < 4; o <<= 1) {
            sums[j] += __shfl_xor_sync(0xffffffffu, sums[j], o);
            sqs[j]  += __shfl_xor_sync(0xffffffffu, sqs[j],  o);
        }
    }
    if (tq == 0) {
#pragma unroll
        for (int j = 0; j < 4; j++) Ps[(r0 + j * 8) * 4 + wn] = make_float2(sums[j], sqs[j]);
    }
    __syncthreads();
    float mus[4], rss[4];
#pragma unroll
    for (int j = 0; j < 4; j++) {
        int row = r0 + j * 8;
        float ssum = 0.f, ssq = 0.f;
#pragma unroll
        for (int w = 0; w < 4; w++) { float2 p = Ps[row * 4 + w]; ssum += p.x; ssq += p.y; }
        float mu  = ssum * (1.f / 128.f);
        float var = ssq * (1.f / 128.f) - mu * mu;
        mus[j] = mu; rss[j] = rsqrtf(var + 1e-5f);
    }
    float2* og2 = (float2*)(out_ret + ((size_t)s * 2048 + b0) * 128);
#pragma unroll
    for (int mt = 0; mt < 2; mt++) {
#pragma unroll
        for (int nt = 0; nt < 4; nt++) {
            int col = wn * 32 + nt * 8 + 2 * tq;
            int rA = r0 + mt * 16, rB = rA + 8;
            float* v = acc2[mt * 4 + nt];
            float muA = mus[mt * 2],     rsA = rss[mt * 2];
            float muB = mus[mt * 2 + 1], rsB = rss[mt * 2 + 1];
            og2[rA * 64 + (col >> 1)] =
                make_float2((v[0] - muA) * rsA * gs[col]     + bs[col],
                            (v[1] - muA) * rsA * gs[col + 1] + bs[col + 1]);
            og2[rB * 64 + (col >> 1)] =
                make_float2((v[2] - muB) * rsB * gs[col]     + bs[col],
                            (v[3] - muB) * rsB * gs[col + 1] + bs[col + 1]);
        }
    }
}

// ---------------------------------------------------------------------------
// Kernel B (persistent): diffs[s-1] = gelu([X_{s-1} | X_s] @ Wb + bb)
// 512 thr = 16 warps (4M x 4N), warp tile 16x32, CTA tile 64 tokens.
// Wb fully resident (stride 260). CTA walks a range of s: X_s reused as
// prev for step s+1; X_{s+1} prefetched into regs during ksteps 16-31.
// ---------------------------------------------------------------------------
#define PB_WB   0                      // 128*260*4 = 133120
#define PB_X0   133120                 // 64*132*4  = 33792
#define PB_X1   166912                 // 33792
#define PB_BB   200704                 // 512
#define PB_SZ   201216
#define PB_SGRP 9                      // s-groups; 32*9 = 288 CTAs
#define PB_SPG  29                     // ceil(255/9)

__global__ __launch_bounds__(512, 1)
void bracket_kernel(const float* __restrict__ src,
                    const float* __restrict__ bb,
                    float* __restrict__ out_diffs, float* __restrict__ cond)
{
    extern __shared__ char smem[];
    const uint32_t sb = smem_u32(smem);
    float* bbs = (float*)(smem + PB_BB);

    const int tid = threadIdx.x, lane = tid & 31, wid = tid >> 5;
    const int group = lane >> 2, tq = lane & 3;
    const int wm = wid & 3, wn = wid >> 2;       // 4M x 4N

    const int b0 = blockIdx.x * 64;
    const int sg = blockIdx.y;
    const int s0 = 1 + sg * PB_SPG;
    const int s1 = min(256, s0 + PB_SPG);
    if (blockIdx.x == 0 && sg == 0 && tid < 3) cond[tid] = 0.f;

    // ---- stage Wb resident (cp.async; 8192 float4) ----
    for (int u = tid; u < 8192; u += 512) {
        int n = u >> 6, k4 = u & 63;
        cp16(sb + PB_WB + (uint32_t)n * 1040 + k4 * 16, &g_Wb[n * 256 + k4 * 4]);
    }
    CP_COMMIT;
    if (tid < 128) bbs[tid] = bb[tid];

    // ---- stage X_{s0-1} -> X0, X_{s0} -> X1 ----
    float* X0 = (float*)(smem + PB_X0);
    float* X1 = (float*)(smem + PB_X1);
#pragma unroll
    for (int i = 0; i < 4; i++) {
        int idx = tid + i * 512;
        int row = idx >> 5, c4 = idx & 31;
        float4 vp = reinterpret_cast<const float4*>(src + ((size_t)(s0 - 1) * 2048 + b0 + row) * 128)[c4];
        float4 vc = reinterpret_cast<const float4*>(src + ((size_t)s0 * 2048 + b0 + row) * 128)[c4];
        *reinterpret_cast<float4*>(&X0[row * 132 + c4 * 4]) =
            make_float4(tf32f(vp.x), tf32f(vp.y), tf32f(vp.z), tf32f(vp.w));
        *reinterpret_cast<float4*>(&X1[row * 132 + c4 * 4]) =
            make_float4(tf32f(vc.x), tf32f(vc.y), tf32f(vc.z), tf32f(vc.w));
    }
    CP_WAIT0;
    __syncthreads();

    // LDSM addressing
    const int lm = lane & 15, lh = lane >> 4;
    const int bn = (lane & 7) + ((lane >> 4) << 3);
    const int bk = ((lane >> 3) & 1) * 16;
    const uint32_t aoff = (uint32_t)(wm * 16 + lm) * 528 + lh * 16;
    const uint32_t bW0  = sb + PB_WB + (uint32_t)(wn * 32 + bn) * 1040 + bk;
    const uint32_t bW1  = bW0 + 16 * 1040;

    uint32_t bufP = sb + PB_X0, bufC = sb + PB_X1;
    float*   bufPf = X0;

    const int rA = wm * 16 + group, rB = rA + 8;
    const int colb = wn * 32 + 2 * tq;

    for (int s = s0; s < s1; ++s) {
        float acc[4][4];
#pragma unroll
        for (int i = 0; i < 4; i++) { acc[i][0] = acc[i][1] = acc[i][2] = acc[i][3] = 0.f; }

        // ---- ksteps 0..15: A from bufP (X_{s-1}) ----
#pragma unroll
        for (int ks = 0; ks < 16; ks++) {
            unsigned A[4], B0f[4], B1f[4];
            LDSM4(A,   bufP + aoff + ks * 32);
            LDSM4(B0f, bW0 + ks * 32);
            LDSM4(B1f, bW1 + ks * 32);
            mma8(acc[0], A, B0f);  mma8(acc[1], A, B0f + 2);
            mma8(acc[2], A, B1f);  mma8(acc[3], A, B1f + 2);
        }
        __syncthreads();   // all warps done reading bufP

        // ---- prefetch X_{s+1} into registers (hidden under ksteps 16-31) ----
        const bool pf = (s + 1 < s1);
        float4 xr[4];
        if (pf) {
#pragma unroll
            for (int i = 0; i < 4; i++) {
                int idx = tid + i * 512;
                int row = idx >> 5, c4 = idx & 31;
                xr[i] = reinterpret_cast<const float4*>(
                            src + ((size_t)(s + 1) * 2048 + b0 + row) * 128)[c4];
            }
        }

        // ---- ksteps 16..31: A from bufC (X_s) ----
#pragma unroll
        for (int ks = 16; ks < 32; ks++) {
            unsigned A[4], B0f[4], B1f[4];
            LDSM4(A,   bufC + aoff + (ks - 16) * 32);
            LDSM4(B0f, bW0 + ks * 32);
            LDSM4(B1f, bW1 + ks * 32);
            mma8(acc[0], A, B0f);  mma8(acc[1], A, B0f + 2);
            mma8(acc[2], A, B1f);  mma8(acc[3], A, B1f + 2);
        }

        // ---- store prefetched X_{s+1} into bufP ----
        if (pf) {
#pragma unroll
            for (int i = 0; i < 4; i++) {
                int idx = tid + i * 512;
                int row = idx >> 5, c4 = idx & 31;
                *reinterpret_cast<float4*>(&bufPf[row * 132 + c4 * 4]) =
                    make_float4(tf32f(xr[i].x), tf32f(xr[i].y), tf32f(xr[i].z), tf32f(xr[i].w));
            }
        }

        // ---- epilogue: gelu(acc + bb) -> diffs[s-1] ----
        {
            float2* og2 = (float2*)(out_diffs + ((size_t)(s - 1) * 2048 + b0) * 128);
#pragma unroll
            for (int nt = 0; nt < 4; nt++) {
                int col = colb + nt * 8;
                float bi0 = bbs[col], bi1 = bbs[col + 1];
                float* v = acc[nt];
                og2[rA * 64 + (col >> 1)] = make_float2(gelu_exact(v[0] + bi0),
                                                        gelu_exact(v[1] + bi1));
                og2[rB * 64 + (col >> 1)] = make_float2(gelu_exact(v[2] + bi0),
                                                        gelu_exact(v[3] + bi1));
            }
        }
        __syncthreads();   // bufP fully rewritten before next step reads it as cur

        // swap: next step's prev = X_s (old cur), cur = X_{s+1} (old prev buf)
        uint32_t tu = bufP; bufP = bufC; bufC = tu;
        bufPf = (bufPf == X0) ? X1 : X0;
        // bufPf must track the buffer that will be REFILLED next step = new bufP?
        // new bufP = old bufC; refill target next step is new bufP's partner...
        // Refill always goes into the buffer just released (old bufP = new bufC).
    }
}

// ---------------------------------------------------------------------------
// launcher
// ---------------------------------------------------------------------------
extern "C" void kernel_launch(void* const* d_in, const int* in_sizes, int n_in,
                              void* d_out, int out_size)
{
    const float* src   = (const float*)d_in[0];
    const float* Wb    = (const float*)d_in[1];
    const float* bb    = (const float*)d_in[2];
    const float* W1    = (const float*)d_in[3];
    const float* b1    = (const float*)d_in[4];
    const float* W2    = (const float*)d_in[5];
    const float* b2    = (const float*)d_in[6];
    const float* gamma = (const float*)d_in[7];
    const float* beta  = (const float*)d_in[8];
    float* out = (float*)d_out;

    cudaFuncSetAttribute(fused_main_kernel, cudaFuncAttributeMaxDynamicSharedMemorySize, FA_SZ);
    cudaFuncSetAttribute(bracket_kernel,    cudaFuncAttributeMaxDynamicSharedMemorySize, PB_SZ);

    prep_weights<<<96, 256>>>(Wb, W1, W2);

    dim3 gA(16, 256);
    dim3 gB(32, PB_SGRP);
    fused_main_kernel<<<gA, 512, FA_SZ>>>(src, b1, b2, gamma, beta, out);
    bracket_kernel<<<gB, 512, PB_SZ>>>(src, bb,
                                       out + RET_ELEMS,
                                       out + RET_ELEMS + DIFF_ELEMS);
}

// round 13
// speedup vs baseline: 1.8442x; 1.2817x over previous
#include <cuda_runtime.h>
#include <cuda_bf16.h>
#include <cstdint>
#include <math.h>

#define RET_ELEMS (256LL * 2048LL * 128LL)
#define DIFF_ELEMS (255LL * 2048LL * 128LL)

// Pre-transposed scratch: Wb tf32-rounded fp32 [n][k]; W1/W2 bf16 [n][k].
__device__ float         g_Wb[128 * 256];
__device__ __nv_bfloat16 g_W1h[256 * 128];
__device__ __nv_bfloat16 g_W2h[128 * 256];

// ---------------------------------------------------------------------------
// helpers
// ---------------------------------------------------------------------------
__device__ __forceinline__ float gelu_exact(float x) {
    return 0.5f * x * (1.0f + erff(x * 0.7071067811865476f));
}
__device__ __forceinline__ unsigned f2tf32(float x) {
    unsigned r; asm("cvt.rna.tf32.f32 %0, %1;" : "=r"(r) : "f"(x)); return r;
}
__device__ __forceinline__ float tf32f(float x) { return __uint_as_float(f2tf32(x)); }

__device__ __forceinline__ uint32_t bfpack2(float a, float b) {
    return (uint32_t)__bfloat16_as_ushort(__float2bfloat16(a)) |
           ((uint32_t)__bfloat16_as_ushort(__float2bfloat16(b)) << 16);
}

__device__ __forceinline__ uint32_t smem_u32(const void* p) {
    uint32_t a;
    asm("{ .reg .u64 t; cvta.to.shared.u64 t, %1; cvt.u32.u64 %0, t; }" : "=r"(a) : "l"(p));
    return a;
}

__device__ __forceinline__ void mma8(float* d, const unsigned* a, const unsigned* b) {
    asm volatile(
        "mma.sync.aligned.m16n8k8.row.col.f32.tf32.tf32.f32 "
        "{%0,%1,%2,%3}, {%4,%5,%6,%7}, {%8,%9}, {%0,%1,%2,%3};"
        : "+f"(d[0]), "+f"(d[1]), "+f"(d[2]), "+f"(d[3])
        : "r"(a[0]), "r"(a[1]), "r"(a[2]), "r"(a[3]), "r"(b[0]), "r"(b[1]));
}
__device__ __forceinline__ void mma16(float* d, const unsigned* a, const unsigned* b) {
    asm volatile(
        "mma.sync.aligned.m16n8k16.row.col.f32.bf16.bf16.f32 "
        "{%0,%1,%2,%3}, {%4,%5,%6,%7}, {%8,%9}, {%0,%1,%2,%3};"
        : "+f"(d[0]), "+f"(d[1]), "+f"(d[2]), "+f"(d[3])
        : "r"(a[0]), "r"(a[1]), "r"(a[2]), "r"(a[3]), "r"(b[0]), "r"(b[1]));
}

#define LDSM4(R, addr) \
    asm volatile("ldmatrix.sync.aligned.m8n8.x4.shared.b16 {%0,%1,%2,%3}, [%4];" \
                 : "=r"((R)[0]), "=r"((R)[1]), "=r"((R)[2]), "=r"((R)[3]) : "r"(addr))

__device__ __forceinline__ void cp16(uint32_t dst, const void* src) {
    asm volatile("cp.async.cg.shared.global [%0], [%1], 16;" :: "r"(dst), "l"(src));
}
#define CP_COMMIT asm volatile("cp.async.commit_group;" ::: "memory")
#define CP_WAIT0  asm volatile("cp.async.wait_group 0;"  ::: "memory")

// ---------------------------------------------------------------------------
// prep: transpose weights into scratch (Wb: tf32 fp32; W1/W2: bf16)
// ---------------------------------------------------------------------------
__global__ void prep_weights(const float* __restrict__ Wb,
                             const float* __restrict__ W1,
                             const float* __restrict__ W2)
{
    int i = blockIdx.x * 256 + threadIdx.x;       // 0 .. 16383
    if (i < 8192) {                               // g_Wb: [128n][256k] fp32 tf32
        int n = i >> 6, k4 = i & 63;
        float4 o;
        o.x = tf32f(Wb[(k4 * 4 + 0) * 128 + n]);
        o.y = tf32f(Wb[(k4 * 4 + 1) * 128 + n]);
        o.z = tf32f(Wb[(k4 * 4 + 2) * 128 + n]);
        o.w = tf32f(Wb[(k4 * 4 + 3) * 128 + n]);
        *reinterpret_cast<float4*>(&g_Wb[n * 256 + k4 * 4]) = o;
    } else if (i < 12288) {                       // g_W1h: [256n][128k] bf16
        int idx = i - 8192;
        int n = idx >> 4, k8 = idx & 15;
        float v[8];
#pragma unroll
        for (int j = 0; j < 8; j++) v[j] = W1[(k8 * 8 + j) * 256 + n];
        uint4 o = { bfpack2(v[0], v[1]), bfpack2(v[2], v[3]),
                    bfpack2(v[4], v[5]), bfpack2(v[6], v[7]) };
        *reinterpret_cast<uint4*>(&g_W1h[n * 128 + k8 * 8]) = o;
    } else {                                      // g_W2h: [128n][256k] bf16
        int idx = i - 12288;
        int n = idx >> 5, k8 = idx & 31;
        float v[8];
#pragma unroll
        for (int j = 0; j < 8; j++) v[j] = W2[(k8 * 8 + j) * 128 + n];
        uint4 o = { bfpack2(v[0], v[1]), bfpack2(v[2], v[3]),
                    bfpack2(v[4], v[5]), bfpack2(v[6], v[7]) };
        *reinterpret_cast<uint4*>(&g_W2h[n * 256 + k8 * 8]) = o;
    }
}

// ---------------------------------------------------------------------------
// Kernel A (bf16): ret = LayerNorm(gelu(gelu(X@W1+b1)@W2+b2) + X)
// 512 thr = 16 warps (4M x 4N). W1/W2 fully resident (bf16). H in 4 chunks.
// Byte strides: W1 272, W2 528, X 272, H 144 (all ≡ 16 mod 128 -> LDSM clean)
// ---------------------------------------------------------------------------
#define FB_W1   0                      // 256*272 = 69632
#define FB_W2   69632                  // 128*528 = 67584
#define FB_X    137216                 // 128*272 = 34816
#define FB_H    172032                 // 128*144 = 18432
#define FB_B1   190464                 // 1024
#define FB_B2   191488                 // 512
#define FB_G    192000                 // 512
#define FB_BE   192512                 // 512
#define FB_PS   193024                 // 4096
#define FB_SZ   197120

__global__ __launch_bounds__(512, 1)
void fused_main_kernel(const float* __restrict__ src,
                       const float* __restrict__ b1, const float* __restrict__ b2,
                       const float* __restrict__ gamma, const float* __restrict__ beta,
                       float* __restrict__ out_ret)
{
    extern __shared__ char smem[];
    const uint32_t sb = smem_u32(smem);
    float* b1s = (float*)(smem + FB_B1);
    float* b2s = (float*)(smem + FB_B2);
    float* gs  = (float*)(smem + FB_G);
    float* bs  = (float*)(smem + FB_BE);
    float2* Ps = (float2*)(smem + FB_PS);

    const int tid = threadIdx.x, lane = tid & 31, wid = tid >> 5;
    const int group = lane >> 2, tq = lane & 3;
    const int wm = wid & 3, wn = wid >> 2;       // 4M x 4N
    const int r0 = wm * 32 + group;

    const int s  = blockIdx.y;
    const int b0 = blockIdx.x * 128;
    const float* Xg = src + ((size_t)s * 2048 + b0) * 128;

    // ---- stage resident weights (cp.async, pre-converted bf16 bytes) ----
    for (int u = tid; u < 4096; u += 512) {       // W1h: 256 rows x 16 cp16
        int n = u >> 4, k8 = u & 15;
        cp16(sb + FB_W1 + (uint32_t)n * 272 + k8 * 16, &g_W1h[n * 128 + k8 * 8]);
    }
    for (int u = tid; u < 4096; u += 512) {       // W2h: 128 rows x 32 cp16
        int n = u >> 5, k8 = u & 31;
        cp16(sb + FB_W2 + (uint32_t)n * 528 + k8 * 16, &g_W2h[n * 256 + k8 * 8]);
    }
    CP_COMMIT;

    // ---- stage X as bf16 (8 floats -> uint4 of 8 bf16 per task) ----
    for (int u = tid; u < 2048; u += 512) {
        int row = u >> 4, c8 = u & 15;
        const float4* p = reinterpret_cast<const float4*>(Xg + row * 128 + c8 * 8);
        float4 lo = p[0], hi = p[1];
        uint4 o = { bfpack2(lo.x, lo.y), bfpack2(lo.z, lo.w),
                    bfpack2(hi.x, hi.y), bfpack2(hi.z, hi.w) };
        *reinterpret_cast<uint4*>(smem + FB_X + row * 272 + c8 * 16) = o;
    }
    if (tid < 256) b1s[tid] = b1[tid];
    if (tid < 128) { b2s[tid] = b2[tid]; gs[tid] = gamma[tid]; bs[tid] = beta[tid]; }
    CP_WAIT0;
    __syncthreads();

    // LDSM addressing (b16 tiles: rows 16B apart halves at +16B)
    const int lm = lane & 15, lh = lane >> 4;            // A: row-in-16, k-half
    const int bn = (lane & 7) + ((lane >> 4) << 3);      // B: n-in-16
    const int bkB = ((lane >> 3) & 1) * 16;              // B: k-half bytes
    const uint32_t aX  = sb + FB_X + (uint32_t)(wm * 32 + lm) * 272 + lh * 16;
    const uint32_t aX1 = aX + 16 * 272;
    const uint32_t bW1b = sb + FB_W1 + (uint32_t)(wn * 16 + bn) * 272 + bkB;  // + c*17408
    const uint32_t aH  = sb + FB_H + (uint32_t)(wm * 32 + lm) * 144 + lh * 16;
    const uint32_t aH1 = aH + 16 * 144;
    const uint32_t bW2b = sb + FB_W2 + (uint32_t)(wn * 32 + bn) * 528 + bkB;  // + c*128
    const uint32_t bW2b1 = bW2b + 16 * 528;

    float acc2[8][4];
#pragma unroll
    for (int i = 0; i < 8; i++) { acc2[i][0] = acc2[i][1] = acc2[i][2] = acc2[i][3] = 0.f; }

#pragma unroll
    for (int c = 0; c < 4; ++c) {
        // ---- GEMM1: Hc = X @ W1c (warp 32x16, K=128 -> 8 k16-steps) ----
        float acc1[4][4];
#pragma unroll
        for (int i = 0; i < 4; i++) { acc1[i][0] = acc1[i][1] = acc1[i][2] = acc1[i][3] = 0.f; }
        {
            const uint32_t bw = bW1b + (uint32_t)c * 17408;   // 64 rows * 272
#pragma unroll
            for (int ks = 0; ks < 8; ks++) {
                unsigned A0[4], A1[4], B[4];
                LDSM4(A0, aX  + ks * 32);
                LDSM4(A1, aX1 + ks * 32);
                LDSM4(B,  bw  + ks * 32);
                mma16(acc1[0], A0, B);  mma16(acc1[1], A0, B + 2);
                mma16(acc1[2], A1, B);  mma16(acc1[3], A1, B + 2);
            }
        }

        // ---- epilogue-1: H = bf16(gelu(acc1 + b1)) ----
#pragma unroll
        for (int mt = 0; mt < 2; mt++) {
#pragma unroll
            for (int nt = 0; nt < 2; nt++) {
                int col = wn * 16 + nt * 8 + 2 * tq;          // 0..63 within chunk
                int rA = r0 + mt * 16, rB = rA + 8;
                float bi0 = b1s[c * 64 + col], bi1 = b1s[c * 64 + col + 1];
                float* v = acc1[mt * 2 + nt];
                *reinterpret_cast<uint32_t*>(smem + FB_H + rA * 144 + col * 2) =
                    bfpack2(gelu_exact(v[0] + bi0), gelu_exact(v[1] + bi1));
                *reinterpret_cast<uint32_t*>(smem + FB_H + rB * 144 + col * 2) =
                    bfpack2(gelu_exact(v[2] + bi0), gelu_exact(v[3] + bi1));
            }
        }
        __syncthreads();   // Hc visible to all warps

        // ---- GEMM2: acc2 += Hc @ W2c (warp 32x32, K=64 -> 4 k16-steps) ----
        {
            const uint32_t bw0 = bW2b  + (uint32_t)c * 128;   // k-slice c*64 bf16
            const uint32_t bw1 = bW2b1 + (uint32_t)c * 128;
#pragma unroll
            for (int ks = 0; ks < 4; ks++) {
                unsigned A0[4], A1[4], B0[4], B1[4];
                LDSM4(A0, aH  + ks * 32);
                LDSM4(A1, aH1 + ks * 32);
                LDSM4(B0, bw0 + ks * 32);
                LDSM4(B1, bw1 + ks * 32);
                mma16(acc2[0], A0, B0);  mma16(acc2[1], A0, B0 + 2);
                mma16(acc2[2], A0, B1);  mma16(acc2[3], A0, B1 + 2);
                mma16(acc2[4], A1, B0);  mma16(acc2[5], A1, B0 + 2);
                mma16(acc2[6], A1, B1);  mma16(acc2[7], A1, B1 + 2);
            }
        }
        __syncthreads();   // GEMM2 done before next chunk overwrites Hc
    }

    // ---- epilogue-2: r = gelu(acc2+b2)+X (fp32 from gmem) ; LayerNorm ----
    float sums[4] = {0, 0, 0, 0}, sqs[4] = {0, 0, 0, 0};
    const float2* Xg2 = (const float2*)Xg;
#pragma unroll
    for (int mt = 0; mt < 2; mt++) {
#pragma unroll
        for (int nt = 0; nt < 4; nt++) {
            int col = wn * 32 + nt * 8 + 2 * tq;
            int rA = r0 + mt * 16, rB = rA + 8;
            float2 xa = Xg2[rA * 64 + (col >> 1)];
            float2 xb = Xg2[rB * 64 + (col >> 1)];
            float* v = acc2[mt * 4 + nt];
            v[0] = gelu_exact(v[0] + b2s[col])     + xa.x;
            v[1] = gelu_exact(v[1] + b2s[col + 1]) + xa.y;
            v[2] = gelu_exact(v[2] + b2s[col])     + xb.x;
            v[3] = gelu_exact(v[3] + b2s[col + 1]) + xb.y;
            sums[mt * 2]     += v[0] + v[1]; sqs[mt * 2]     += v[0] * v[0] + v[1] * v[1];
            sums[mt * 2 + 1] += v[2] + v[3]; sqs[mt * 2 + 1] += v[2] * v[2] + v[3] * v[3];
        }
    }
#pragma unroll
    for (int j = 0; j < 4; j++) {
#pragma unroll
        for (int o = 1; o < 4; o <<= 1) {
            sums[j] += __shfl_xor_sync(0xffffffffu, sums[j], o);
            sqs[j]  += __shfl_xor_sync(0xffffffffu, sqs[j],  o);
        }
    }
    if (tq == 0) {
#pragma unroll
        for (int j = 0; j < 4; j++) Ps[(r0 + j * 8) * 4 + wn] = make_float2(sums[j], sqs[j]);
    }
    __syncthreads();
    float mus[4], rss[4];
#pragma unroll
    for (int j = 0; j < 4; j++) {
        int row = r0 + j * 8;
        float ssum = 0.f, ssq = 0.f;
#pragma unroll
        for (int w = 0; w < 4; w++) { float2 p = Ps[row * 4 + w]; ssum += p.x; ssq += p.y; }
        float mu  = ssum * (1.f / 128.f);
        float var = ssq * (1.f / 128.f) - mu * mu;
        mus[j] = mu; rss[j] = rsqrtf(var + 1e-5f);
    }
    float2* og2 = (float2*)(out_ret + ((size_t)s * 2048 + b0) * 128);
#pragma unroll
    for (int mt = 0; mt < 2; mt++) {
#pragma unroll
        for (int nt = 0; nt < 4; nt++) {
            int col = wn * 32 + nt * 8 + 2 * tq;
            int rA = r0 + mt * 16, rB = rA + 8;
            float* v = acc2[mt * 4 + nt];
            float muA = mus[mt * 2],     rsA = rss[mt * 2];
            float muB = mus[mt * 2 + 1], rsB = rss[mt * 2 + 1];
            og2[rA * 64 + (col >> 1)] =
                make_float2((v[0] - muA) * rsA * gs[col]     + bs[col],
                            (v[1] - muA) * rsA * gs[col + 1] + bs[col + 1]);
            og2[rB * 64 + (col >> 1)] =
                make_float2((v[2] - muB) * rsB * gs[col]     + bs[col],
                            (v[3] - muB) * rsB * gs[col + 1] + bs[col + 1]);
        }
    }
}

// ---------------------------------------------------------------------------
// Kernel B (persistent, tf32 — unchanged from R11)
// ---------------------------------------------------------------------------
#define PB_WB   0                      // 128*260*4 = 133120
#define PB_X0   133120                 // 64*132*4  = 33792
#define PB_X1   166912                 // 33792
#define PB_BB   200704                 // 512
#define PB_SZ   201216
#define PB_SGRP 9
#define PB_SPG  29

__global__ __launch_bounds__(512, 1)
void bracket_kernel(const float* __restrict__ src,
                    const float* __restrict__ bb,
                    float* __restrict__ out_diffs, float* __restrict__ cond)
{
    extern __shared__ char smem[];
    const uint32_t sb = smem_u32(smem);
    float* bbs = (float*)(smem + PB_BB);

    const int tid = threadIdx.x, lane = tid & 31, wid = tid >> 5;
    const int group = lane >> 2, tq = lane & 3;
    const int wm = wid & 3, wn = wid >> 2;

    const int b0 = blockIdx.x * 64;
    const int sg = blockIdx.y;
    const int s0 = 1 + sg * PB_SPG;
    const int s1 = min(256, s0 + PB_SPG);
    if (blockIdx.x == 0 && sg == 0 && tid < 3) cond[tid] = 0.f;

    for (int u = tid; u < 8192; u += 512) {
        int n = u >> 6, k4 = u & 63;
        cp16(sb + PB_WB + (uint32_t)n * 1040 + k4 * 16, &g_Wb[n * 256 + k4 * 4]);
    }
    CP_COMMIT;
    if (tid < 128) bbs[tid] = bb[tid];

    float* X0 = (float*)(smem + PB_X0);
    float* X1 = (float*)(smem + PB_X1);
#pragma unroll
    for (int i = 0; i < 4; i++) {
        int idx = tid + i * 512;
        int row = idx >> 5, c4 = idx & 31;
        float4 vp = reinterpret_cast<const float4*>(src + ((size_t)(s0 - 1) * 2048 + b0 + row) * 128)[c4];
        float4 vc = reinterpret_cast<const float4*>(src + ((size_t)s0 * 2048 + b0 + row) * 128)[c4];
        *reinterpret_cast<float4*>(&X0[row * 132 + c4 * 4]) =
            make_float4(tf32f(vp.x), tf32f(vp.y), tf32f(vp.z), tf32f(vp.w));
        *reinterpret_cast<float4*>(&X1[row * 132 + c4 * 4]) =
            make_float4(tf32f(vc.x), tf32f(vc.y), tf32f(vc.z), tf32f(vc.w));
    }
    CP_WAIT0;
    __syncthreads();

    const int lm = lane & 15, lh = lane >> 4;
    const int bn = (lane & 7) + ((lane >> 4) << 3);
    const int bk = ((lane >> 3) & 1) * 16;
    const uint32_t aoff = (uint32_t)(wm * 16 + lm) * 528 + lh * 16;
    const uint32_t bW0  = sb + PB_WB + (uint32_t)(wn * 32 + bn) * 1040 + bk;
    const uint32_t bW1  = bW0 + 16 * 1040;

    uint32_t bufP = sb + PB_X0, bufC = sb + PB_X1;
    float*   bufPf = X0;

    const int rA = wm * 16 + group, rB = rA + 8;
    const int colb = wn * 32 + 2 * tq;

    for (int s = s0; s < s1; ++s) {
        float acc[4][4];
#pragma unroll
        for (int i = 0; i < 4; i++) { acc[i][0] = acc[i][1] = acc[i][2] = acc[i][3] = 0.f; }

#pragma unroll
        for (int ks = 0; ks < 16; ks++) {
            unsigned A[4], B0f[4], B1f[4];
            LDSM4(A,   bufP + aoff + ks * 32);
            LDSM4(B0f, bW0 + ks * 32);
            LDSM4(B1f, bW1 + ks * 32);
            mma8(acc[0], A, B0f);  mma8(acc[1], A, B0f + 2);
            mma8(acc[2], A, B1f);  mma8(acc[3], A, B1f + 2);
        }
        __syncthreads();

        const bool pf = (s + 1 < s1);
        float4 xr[4];
        if (pf) {
#pragma unroll
            for (int i = 0; i < 4; i++) {
                int idx = tid + i * 512;
                int row = idx >> 5, c4 = idx & 31;
                xr[i] = reinterpret_cast<const float4*>(
                            src + ((size_t)(s + 1) * 2048 + b0 + row) * 128)[c4];
            }
        }

#pragma unroll
        for (int ks = 16; ks < 32; ks++) {
            unsigned A[4], B0f[4], B1f[4];
            LDSM4(A,   bufC + aoff + (ks - 16) * 32);
            LDSM4(B0f, bW0 + ks * 32);
            LDSM4(B1f, bW1 + ks * 32);
            mma8(acc[0], A, B0f);  mma8(acc[1], A, B0f + 2);
            mma8(acc[2], A, B1f);  mma8(acc[3], A, B1f + 2);
        }

        if (pf) {
#pragma unroll
            for (int i = 0; i < 4; i++) {
                int idx = tid + i * 512;
                int row = idx >> 5, c4 = idx & 31;
                *reinterpret_cast<float4*>(&bufPf[row * 132 + c4 * 4]) =
                    make_float4(tf32f(xr[i].x), tf32f(xr[i].y), tf32f(xr[i].z), tf32f(xr[i].w));
            }
        }

        {
            float2* og2 = (float2*)(out_diffs + ((size_t)(s - 1) * 2048 + b0) * 128);
#pragma unroll
            for (int nt = 0; nt < 4; nt++) {
                int col = colb + nt * 8;
                float bi0 = bbs[col], bi1 = bbs[col + 1];
                float* v = acc[nt];
                og2[rA * 64 + (col >> 1)] = make_float2(gelu_exact(v[0] + bi0),
                                                        gelu_exact(v[1] + bi1));
                og2[rB * 64 + (col >> 1)] = make_float2(gelu_exact(v[2] + bi0),
                                                        gelu_exact(v[3] + bi1));
            }
        }
        __syncthreads();

        uint32_t tu = bufP; bufP = bufC; bufC = tu;
        bufPf = (bufPf == X0) ? X1 : X0;
    }
}

// ---------------------------------------------------------------------------
// launcher
// ---------------------------------------------------------------------------
extern "C" void kernel_launch(void* const* d_in, const int* in_sizes, int n_in,
                              void* d_out, int out_size)
{
    const float* src   = (const float*)d_in[0];
    const float* Wb    = (const float*)d_in[1];
    const float* bb    = (const float*)d_in[2];
    const float* W1    = (const float*)d_in[3];
    const float* b1    = (const float*)d_in[4];
    const float* W2    = (const float*)d_in[5];
    const float* b2    = (const float*)d_in[6];
    const float* gamma = (const float*)d_in[7];
    const float* beta  = (const float*)d_in[8];
    float* out = (float*)d_out;

    cudaFuncSetAttribute(fused_main_kernel, cudaFuncAttributeMaxDynamicSharedMemorySize, FB_SZ);
    cudaFuncSetAttribute(bracket_kernel,    cudaFuncAttributeMaxDynamicSharedMemorySize, PB_SZ);

    prep_weights<<<64, 256>>>(Wb, W1, W2);

    dim3 gA(16, 256);
    dim3 gB(32, PB_SGRP);
    fused_main_kernel<<<gA, 512, FB_SZ>>>(src, b1, b2, gamma, beta, out);
    bracket_kernel<<<gB, 512, PB_SZ>>>(src, bb,
                                       out + RET_ELEMS,
                                       out + RET_ELEMS + DIFF_ELEMS);
}

// round 15
// speedup vs baseline: 2.1739x; 1.1788x over previous
#include <cuda_runtime.h>
#include <cuda_bf16.h>
#include <cuda_fp16.h>
#include <cstdint>
#include <math.h>

#define RET_ELEMS (256LL * 2048LL * 128LL)
#define DIFF_ELEMS (255LL * 2048LL * 128LL)

// Pre-transposed scratch: Wb fp16 [n][k]; W1/W2 bf16 [n][k].
__device__ __half        g_Wbh[128 * 256];
__device__ __nv_bfloat16 g_W1h[256 * 128];
__device__ __nv_bfloat16 g_W2h[128 * 256];

// ---------------------------------------------------------------------------
// helpers
// ---------------------------------------------------------------------------
__device__ __forceinline__ float gelu_exact(float x) {
    return 0.5f * x * (1.0f + erff(x * 0.7071067811865476f));
}
__device__ __forceinline__ uint32_t bfpack2(float a, float b) {
    return (uint32_t)__bfloat16_as_ushort(__float2bfloat16(a)) |
           ((uint32_t)__bfloat16_as_ushort(__float2bfloat16(b)) << 16);
}
__device__ __forceinline__ uint32_t hpack2(float a, float b) {
    return (uint32_t)__half_as_ushort(__float2half_rn(a)) |
           ((uint32_t)__half_as_ushort(__float2half_rn(b)) << 16);
}

__device__ __forceinline__ uint32_t smem_u32(const void* p) {
    uint32_t a;
    asm("{ .reg .u64 t; cvta.to.shared.u64 t, %1; cvt.u32.u64 %0, t; }" : "=r"(a) : "l"(p));
    return a;
}

__device__ __forceinline__ void mma16bf(float* d, const unsigned* a, const unsigned* b) {
    asm volatile(
        "mma.sync.aligned.m16n8k16.row.col.f32.bf16.bf16.f32 "
        "{%0,%1,%2,%3}, {%4,%5,%6,%7}, {%8,%9}, {%0,%1,%2,%3};"
        : "+f"(d[0]), "+f"(d[1]), "+f"(d[2]), "+f"(d[3])
        : "r"(a[0]), "r"(a[1]), "r"(a[2]), "r"(a[3]), "r"(b[0]), "r"(b[1]));
}
__device__ __forceinline__ void mma16h(float* d, const unsigned* a, const unsigned* b) {
    asm volatile(
        "mma.sync.aligned.m16n8k16.row.col.f32.f16.f16.f32 "
        "{%0,%1,%2,%3}, {%4,%5,%6,%7}, {%8,%9}, {%0,%1,%2,%3};"
        : "+f"(d[0]), "+f"(d[1]), "+f"(d[2]), "+f"(d[3])
        : "r"(a[0]), "r"(a[1]), "r"(a[2]), "r"(a[3]), "r"(b[0]), "r"(b[1]));
}

#define LDSM4(R, addr) \
    asm volatile("ldmatrix.sync.aligned.m8n8.x4.shared.b16 {%0,%1,%2,%3}, [%4];" \
                 : "=r"((R)[0]), "=r"((R)[1]), "=r"((R)[2]), "=r"((R)[3]) : "r"(addr))

__device__ __forceinline__ void cp16(uint32_t dst, const void* src) {
    asm volatile("cp.async.cg.shared.global [%0], [%1], 16;" :: "r"(dst), "l"(src));
}
#define CP_COMMIT asm volatile("cp.async.commit_group;" ::: "memory")
#define CP_WAIT0  asm volatile("cp.async.wait_group 0;"  ::: "memory")

// ---------------------------------------------------------------------------
// prep: transpose weights into scratch (Wb: fp16; W1/W2: bf16)
// ---------------------------------------------------------------------------
__global__ void prep_weights(const float* __restrict__ Wb,
                             const float* __restrict__ W1,
                             const float* __restrict__ W2)
{
    int i = blockIdx.x * 256 + threadIdx.x;
    if (i < 4096) {                               // g_Wbh: [128n][256k] fp16
        int n = i >> 5, k8 = i & 31;
        float v[8];
#pragma unroll
        for (int j = 0; j < 8; j++) v[j] = Wb[(k8 * 8 + j) * 128 + n];
        uint4 o = { hpack2(v[0], v[1]), hpack2(v[2], v[3]),
                    hpack2(v[4], v[5]), hpack2(v[6], v[7]) };
        *reinterpret_cast<uint4*>(&g_Wbh[n * 256 + k8 * 8]) = o;
    } else if (i < 8192) {                        // g_W1h: [256n][128k] bf16
        int idx = i - 4096;
        int n = idx >> 4, k8 = idx & 15;
        float v[8];
#pragma unroll
        for (int j = 0; j < 8; j++) v[j] = W1[(k8 * 8 + j) * 256 + n];
        uint4 o = { bfpack2(v[0], v[1]), bfpack2(v[2], v[3]),
                    bfpack2(v[4], v[5]), bfpack2(v[6], v[7]) };
        *reinterpret_cast<uint4*>(&g_W1h[n * 128 + k8 * 8]) = o;
    } else if (i < 12288) {                       // g_W2h: [128n][256k] bf16
        int idx = i - 8192;
        int n = idx >> 5, k8 = idx & 31;
        float v[8];
#pragma unroll
        for (int j = 0; j < 8; j++) v[j] = W2[(k8 * 8 + j) * 128 + n];
        uint4 o = { bfpack2(v[0], v[1]), bfpack2(v[2], v[3]),
                    bfpack2(v[4], v[5]), bfpack2(v[6], v[7]) };
        *reinterpret_cast<uint4*>(&g_W2h[n * 256 + k8 * 8]) = o;
    }
}

// ---------------------------------------------------------------------------
// Kernel A (bf16): ret = LayerNorm(gelu(gelu(X@W1+b1)@W2+b2) + X)  (R13, proven)
// ---------------------------------------------------------------------------
#define FB_W1   0
#define FB_W2   69632
#define FB_X    137216
#define FB_H    172032
#define FB_B1   190464
#define FB_B2   191488
#define FB_G    192000
#define FB_BE   192512
#define FB_PS   193024
#define FB_SZ   197120

__global__ __launch_bounds__(512, 1)
void fused_main_kernel(const float* __restrict__ src,
                       const float* __restrict__ b1, const float* __restrict__ b2,
                       const float* __restrict__ gamma, const float* __restrict__ beta,
                       float* __restrict__ out_ret)
{
    extern __shared__ char smem[];
    const uint32_t sb = smem_u32(smem);
    float* b1s = (float*)(smem + FB_B1);
    float* b2s = (float*)(smem + FB_B2);
    float* gs  = (float*)(smem + FB_G);
    float* bs  = (float*)(smem + FB_BE);
    float2* Ps = (float2*)(smem + FB_PS);

    const int tid = threadIdx.x, lane = tid & 31, wid = tid >> 5;
    const int group = lane >> 2, tq = lane & 3;
    const int wm = wid & 3, wn = wid >> 2;
    const int r0 = wm * 32 + group;

    const int s  = blockIdx.y;
    const int b0 = blockIdx.x * 128;
    const float* Xg = src + ((size_t)s * 2048 + b0) * 128;

    for (int u = tid; u < 4096; u += 512) {
        int n = u >> 4, k8 = u & 15;
        cp16(sb + FB_W1 + (uint32_t)n * 272 + k8 * 16, &g_W1h[n * 128 + k8 * 8]);
    }
    for (int u = tid; u < 4096; u += 512) {
        int n = u >> 5, k8 = u & 31;
        cp16(sb + FB_W2 + (uint32_t)n * 528 + k8 * 16, &g_W2h[n * 256 + k8 * 8]);
    }
    CP_COMMIT;

    for (int u = tid; u < 2048; u += 512) {
        int row = u >> 4, c8 = u & 15;
        const float4* p = reinterpret_cast<const float4*>(Xg + row * 128 + c8 * 8);
        float4 lo = p[0], hi = p[1];
        uint4 o = { bfpack2(lo.x, lo.y), bfpack2(lo.z, lo.w),
                    bfpack2(hi.x, hi.y), bfpack2(hi.z, hi.w) };
        *reinterpret_cast<uint4*>(smem + FB_X + row * 272 + c8 * 16) = o;
    }
    if (tid < 256) b1s[tid] = b1[tid];
    if (tid < 128) { b2s[tid] = b2[tid]; gs[tid] = gamma[tid]; bs[tid] = beta[tid]; }
    CP_WAIT0;
    __syncthreads();

    const int lm = lane & 15, lh = lane >> 4;
    const int bn = (lane & 7) + ((lane >> 4) << 3);
    const int bkB = ((lane >> 3) & 1) * 16;
    const uint32_t aX  = sb + FB_X + (uint32_t)(wm * 32 + lm) * 272 + lh * 16;
    const uint32_t aX1 = aX + 16 * 272;
    const uint32_t bW1b = sb + FB_W1 + (uint32_t)(wn * 16 + bn) * 272 + bkB;
    const uint32_t aH  = sb + FB_H + (uint32_t)(wm * 32 + lm) * 144 + lh * 16;
    const uint32_t aH1 = aH + 16 * 144;
    const uint32_t bW2b = sb + FB_W2 + (uint32_t)(wn * 32 + bn) * 528 + bkB;
    const uint32_t bW2b1 = bW2b + 16 * 528;

    float acc2[8][4];
#pragma unroll
    for (int i = 0; i < 8; i++) { acc2[i][0] = acc2[i][1] = acc2[i][2] = acc2[i][3] = 0.f; }

#pragma unroll
    for (int c = 0; c < 4; ++c) {
        float acc1[4][4];
#pragma unroll
        for (int i = 0; i < 4; i++) { acc1[i][0] = acc1[i][1] = acc1[i][2] = acc1[i][3] = 0.f; }
        {
            const uint32_t bw = bW1b + (uint32_t)c * 17408;
#pragma unroll
            for (int ks = 0; ks < 8; ks++) {
                unsigned A0[4], A1[4], B[4];
                LDSM4(A0, aX  + ks * 32);
                LDSM4(A1, aX1 + ks * 32);
                LDSM4(B,  bw  + ks * 32);
                mma16bf(acc1[0], A0, B);  mma16bf(acc1[1], A0, B + 2);
                mma16bf(acc1[2], A1, B);  mma16bf(acc1[3], A1, B + 2);
            }
        }

#pragma unroll
        for (int mt = 0; mt < 2; mt++) {
#pragma unroll
            for (int nt = 0; nt < 2; nt++) {
                int col = wn * 16 + nt * 8 + 2 * tq;
                int rA = r0 + mt * 16, rB = rA + 8;
                float bi0 = b1s[c * 64 + col], bi1 = b1s[c * 64 + col + 1];
                float* v = acc1[mt * 2 + nt];
                *reinterpret_cast<uint32_t*>(smem + FB_H + rA * 144 + col * 2) =
                    bfpack2(gelu_exact(v[0] + bi0), gelu_exact(v[1] + bi1));
                *reinterpret_cast<uint32_t*>(smem + FB_H + rB * 144 + col * 2) =
                    bfpack2(gelu_exact(v[2] + bi0), gelu_exact(v[3] + bi1));
            }
        }
        __syncthreads();

        {
            const uint32_t bw0 = bW2b  + (uint32_t)c * 128;
            const uint32_t bw1 = bW2b1 + (uint32_t)c * 128;
#pragma unroll
            for (int ks = 0; ks < 4; ks++) {
                unsigned A0[4], A1[4], B0[4], B1[4];
                LDSM4(A0, aH  + ks * 32);
                LDSM4(A1, aH1 + ks * 32);
                LDSM4(B0, bw0 + ks * 32);
                LDSM4(B1, bw1 + ks * 32);
                mma16bf(acc2[0], A0, B0);  mma16bf(acc2[1], A0, B0 + 2);
                mma16bf(acc2[2], A0, B1);  mma16bf(acc2[3], A0, B1 + 2);
                mma16bf(acc2[4], A1, B0);  mma16bf(acc2[5], A1, B0 + 2);
                mma16bf(acc2[6], A1, B1);  mma16bf(acc2[7], A1, B1 + 2);
            }
        }
        __syncthreads();
    }

    float sums[4] = {0, 0, 0, 0}, sqs[4] = {0, 0, 0, 0};
    const float2* Xg2 = (const float2*)Xg;
#pragma unroll
    for (int mt = 0; mt < 2; mt++) {
#pragma unroll
        for (int nt = 0; nt < 4; nt++) {
            int col = wn * 32 + nt * 8 + 2 * tq;
            int rA = r0 + mt * 16, rB = rA + 8;
            float2 xa = Xg2[rA * 64 + (col >> 1)];
            float2 xb = Xg2[rB * 64 + (col >> 1)];
            float* v = acc2[mt * 4 + nt];
            v[0] = gelu_exact(v[0] + b2s[col])     + xa.x;
            v[1] = gelu_exact(v[1] + b2s[col + 1]) + xa.y;
            v[2] = gelu_exact(v[2] + b2s[col])     + xb.x;
            v[3] = gelu_exact(v[3] + b2s[col + 1]) + xb.y;
            sums[mt * 2]     += v[0] + v[1]; sqs[mt * 2]     += v[0] * v[0] + v[1] * v[1];
            sums[mt * 2 + 1] += v[2] + v[3]; sqs[mt * 2 + 1] += v[2] * v[2] + v[3] * v[3];
        }
    }
#pragma unroll
    for (int j = 0; j < 4; j++) {
#pragma unroll
        for (int o = 1; o < 4; o <<= 1) {
            sums[j] += __shfl_xor_sync(0xffffffffu, sums[j], o);
            sqs[j]  += __shfl_xor_sync(0xffffffffu, sqs[j],  o);
        }
    }
    if (tq == 0) {
#pragma unroll
        for (int j = 0; j < 4; j++) Ps[(r0 + j * 8) * 4 + wn] = make_float2(sums[j], sqs[j]);
    }
    __syncthreads();
    float mus[4], rss[4];
#pragma unroll
    for (int j = 0; j < 4; j++) {
        int row = r0 + j * 8;
        float ssum = 0.f, ssq = 0.f;
#pragma unroll
        for (int w = 0; w < 4; w++) { float2 p = Ps[row * 4 + w]; ssum += p.x; ssq += p.y; }
        float mu  = ssum * (1.f / 128.f);
        float var = ssq * (1.f / 128.f) - mu * mu;
        mus[j] = mu; rss[j] = rsqrtf(var + 1e-5f);
    }
    float2* og2 = (float2*)(out_ret + ((size_t)s * 2048 + b0) * 128);
#pragma unroll
    for (int mt = 0; mt < 2; mt++) {
#pragma unroll
        for (int nt = 0; nt < 4; nt++) {
            int col = wn * 32 + nt * 8 + 2 * tq;
            int rA = r0 + mt * 16, rB = rA + 8;
            float* v = acc2[mt * 4 + nt];
            float muA = mus[mt * 2],     rsA = rss[mt * 2];
            float muB = mus[mt * 2 + 1], rsB = rss[mt * 2 + 1];
            og2[rA * 64 + (col >> 1)] =
                make_float2((v[0] - muA) * rsA * gs[col]     + bs[col],
                            (v[1] - muA) * rsA * gs[col + 1] + bs[col + 1]);
            og2[rB * 64 + (col >> 1)] =
                make_float2((v[2] - muB) * rsB * gs[col]     + bs[col],
                            (v[3] - muB) * rsB * gs[col + 1] + bs[col + 1]);
        }
    }
}

// ---------------------------------------------------------------------------
// Kernel B (persistent, fp16): diffs[s-1] = gelu([X_{s-1}|X_s] @ Wb + bb)
// Compile-time buffer roles: step(P,C) instantiated with fixed (X0,X1)/(X1,X0).
// ---------------------------------------------------------------------------
#define PH_WB   0                      // 128*528 = 67584
#define PH_X0   67584                  // 128*272 = 34816
#define PH_X1   102400                 // 34816
#define PH_BB   137216                 // 512
#define PH_SZ   137728
#define PH_SGRP 17                     // 17 * 15 = 255 steps exactly
#define PH_SPG  15

__global__ __launch_bounds__(512, 1)
void bracket_kernel(const float* __restrict__ src,
                    const float* __restrict__ bb,
                    float* __restrict__ out_diffs, float* __restrict__ cond)
{
    extern __shared__ char smem[];
    const uint32_t sb = smem_u32(smem);
    float* bbs = (float*)(smem + PH_BB);
    char* X0g = smem + PH_X0;
    char* X1g = smem + PH_X1;

    const int tid = threadIdx.x, lane = tid & 31, wid = tid >> 5;
    const int group = lane >> 2, tq = lane & 3;
    const int wm = wid & 3, wn = wid >> 2;       // 4M x 4N
    const int r0 = wm * 32 + group;

    const int b0 = blockIdx.x * 128;
    const int sg = blockIdx.y;
    const int s0 = 1 + sg * PH_SPG;
    const int sEnd = s0 + PH_SPG;                // exclusive; 17*15 = 255 exact
    if (blockIdx.x == 0 && sg == 0 && tid < 3) cond[tid] = 0.f;

    // ---- stage Wb fp16 resident ----
    for (int u = tid; u < 4096; u += 512) {
        int n = u >> 5, k8 = u & 31;
        cp16(sb + PH_WB + (uint32_t)n * 528 + k8 * 16, &g_Wbh[n * 256 + k8 * 8]);
    }
    CP_COMMIT;
    if (tid < 128) bbs[tid] = bb[tid];

    // ---- stage X_{s0-1} -> X0, X_{s0} -> X1 (fp16, stride 272) ----
#pragma unroll
    for (int i = 0; i < 4; i++) {
        int idx = tid + i * 512;
        int row = idx >> 4, c8 = idx & 15;
        const float4* pp = reinterpret_cast<const float4*>(
            src + ((size_t)(s0 - 1) * 2048 + b0 + row) * 128 + c8 * 8);
        const float4* pc = reinterpret_cast<const float4*>(
            src + ((size_t)s0 * 2048 + b0 + row) * 128 + c8 * 8);
        float4 pl = pp[0], ph = pp[1], cl = pc[0], ch = pc[1];
        *reinterpret_cast<uint4*>(X0g + row * 272 + c8 * 16) =
            make_uint4(hpack2(pl.x, pl.y), hpack2(pl.z, pl.w),
                       hpack2(ph.x, ph.y), hpack2(ph.z, ph.w));
        *reinterpret_cast<uint4*>(X1g + row * 272 + c8 * 16) =
            make_uint4(hpack2(cl.x, cl.y), hpack2(cl.z, cl.w),
                       hpack2(ch.x, ch.y), hpack2(ch.z, ch.w));
    }
    CP_WAIT0;
    __syncthreads();

    // LDSM addressing (proven pattern from fused kernel)
    const int lm = lane & 15, lh = lane >> 4;
    const int bn = (lane & 7) + ((lane >> 4) << 3);
    const int bkB = ((lane >> 3) & 1) * 16;
    const uint32_t aoff0 = (uint32_t)(wm * 32 + lm) * 272 + lh * 16;
    const uint32_t aoff1 = aoff0 + 16 * 272;
    const uint32_t bW0 = sb + PH_WB + (uint32_t)(wn * 32 + bn) * 528 + bkB;
    const uint32_t bW1 = bW0 + 16 * 528;

    // One persistent step: P holds X_{s-1} (consumed then refilled with X_{s+1}),
    // C holds X_s. Pg = generic pointer matching P.
    auto do_step = [&](int s, uint32_t P, uint32_t C, char* Pg) {
        float acc[8][4];
#pragma unroll
        for (int i = 0; i < 8; i++) { acc[i][0] = acc[i][1] = acc[i][2] = acc[i][3] = 0.f; }

        // ksteps 0..7: A = X_{s-1} (P), B = Wb k 0..127
#pragma unroll
        for (int ks = 0; ks < 8; ks++) {
            unsigned A0[4], A1[4], B0f[4], B1f[4];
            LDSM4(A0,  P + aoff0 + ks * 32);
            LDSM4(A1,  P + aoff1 + ks * 32);
            LDSM4(B0f, bW0 + ks * 32);
            LDSM4(B1f, bW1 + ks * 32);
            mma16h(acc[0], A0, B0f);  mma16h(acc[1], A0, B0f + 2);
            mma16h(acc[2], A0, B1f);  mma16h(acc[3], A0, B1f + 2);
            mma16h(acc[4], A1, B0f);  mma16h(acc[5], A1, B0f + 2);
            mma16h(acc[6], A1, B1f);  mma16h(acc[7], A1, B1f + 2);
        }
        __syncthreads();   // all warps done reading P

        const bool pf = (s + 1 < sEnd);
        float4 xr[8];
        if (pf) {
#pragma unroll
            for (int i = 0; i < 4; i++) {
                int idx = tid + i * 512;
                int row = idx >> 4, c8 = idx & 15;
                const float4* p = reinterpret_cast<const float4*>(
                    src + ((size_t)(s + 1) * 2048 + b0 + row) * 128 + c8 * 8);
                xr[i * 2]     = p[0];
                xr[i * 2 + 1] = p[1];
            }
        }

        // ksteps 8..15: A = X_s (C), B = Wb k 128..255
#pragma unroll
        for (int ks = 8; ks < 16; ks++) {
            unsigned A0[4], A1[4], B0f[4], B1f[4];
            LDSM4(A0,  C + aoff0 + (ks - 8) * 32);
            LDSM4(A1,  C + aoff1 + (ks - 8) * 32);
            LDSM4(B0f, bW0 + ks * 32);
            LDSM4(B1f, bW1 + ks * 32);
            mma16h(acc[0], A0, B0f);  mma16h(acc[1], A0, B0f + 2);
            mma16h(acc[2], A0, B1f);  mma16h(acc[3], A0, B1f + 2);
            mma16h(acc[4], A1, B0f);  mma16h(acc[5], A1, B0f + 2);
            mma16h(acc[6], A1, B1f);  mma16h(acc[7], A1, B1f + 2);
        }

        // refill P with X_{s+1}
        if (pf) {
#pragma unroll
            for (int i = 0; i < 4; i++) {
                int idx = tid + i * 512;
                int row = idx >> 4, c8 = idx & 15;
                float4 lo = xr[i * 2], hi = xr[i * 2 + 1];
                *reinterpret_cast<uint4*>(Pg + row * 272 + c8 * 16) =
                    make_uint4(hpack2(lo.x, lo.y), hpack2(lo.z, lo.w),
                               hpack2(hi.x, hi.y), hpack2(hi.z, hi.w));
            }
        }

        // epilogue: gelu(acc + bb) -> diffs[s-1]
        {
            float2* og2 = (float2*)(out_diffs + ((size_t)(s - 1) * 2048 + b0) * 128);
#pragma unroll
            for (int mt = 0; mt < 2; mt++) {
#pragma unroll
                for (int nt = 0; nt < 4; nt++) {
                    int col = wn * 32 + nt * 8 + 2 * tq;
                    int rA = r0 + mt * 16, rB = rA + 8;
                    float bi0 = bbs[col], bi1 = bbs[col + 1];
                    float* v = acc[mt * 4 + nt];
                    og2[rA * 64 + (col >> 1)] = make_float2(gelu_exact(v[0] + bi0),
                                                            gelu_exact(v[1] + bi1));
                    og2[rB * 64 + (col >> 1)] = make_float2(gelu_exact(v[2] + bi0),
                                                            gelu_exact(v[3] + bi1));
                }
            }
        }
        __syncthreads();   // P refill visible before next step reads it as C
    };

    // 15 steps with compile-time buffer roles: (X0,X1), then 7 x [(X1,X0),(X0,X1)]
    int s = s0;
    do_step(s, sb + PH_X0, sb + PH_X1, X0g); ++s;
#pragma unroll 1
    for (int it = 0; it < 7; ++it) {
        do_step(s, sb + PH_X1, sb + PH_X0, X1g); ++s;
        do_step(s, sb + PH_X0, sb + PH_X1, X0g); ++s;
    }
}

// ---------------------------------------------------------------------------
// launcher
// ---------------------------------------------------------------------------
extern "C" void kernel_launch(void* const* d_in, const int* in_sizes, int n_in,
                              void* d_out, int out_size)
{
    const float* src   = (const float*)d_in[0];
    const float* Wb    = (const float*)d_in[1];
    const float* bb    = (const float*)d_in[2];
    const float* W1    = (const float*)d_in[3];
    const float* b1    = (const float*)d_in[4];
    const float* W2    = (const float*)d_in[5];
    const float* b2    = (const float*)d_in[6];
    const float* gamma = (const float*)d_in[7];
    const float* beta  = (const float*)d_in[8];
    float* out = (float*)d_out;

    cudaFuncSetAttribute(fused_main_kernel, cudaFuncAttributeMaxDynamicSharedMemorySize, FB_SZ);
    cudaFuncSetAttribute(bracket_kernel,    cudaFuncAttributeMaxDynamicSharedMemorySize, PH_SZ);

    prep_weights<<<48, 256>>>(Wb, W1, W2);

    dim3 gA(16, 256);
    dim3 gB(16, PH_SGRP);
    fused_main_kernel<<<gA, 512, FB_SZ>>>(src, b1, b2, gamma, beta, out);
    bracket_kernel<<<gB, 512, PH_SZ>>>(src, bb,
                                       out + RET_ELEMS,
                                       out + RET_ELEMS + DIFF_ELEMS);
}